// round 6
// baseline (speedup 1.0000x reference)
#include <cuda_runtime.h>
#include <cuda_bf16.h>
#include <math.h>
#include <stdint.h>

#define BB 4
#define SS 4096
#define DD 128
#define HH 256
#define ROWS (BB*SS)   // 16384

typedef __nv_bfloat16 bf16;
typedef __nv_bfloat162 bf162;

// ---------------- scratch (no allocations allowed) ----------------
__device__ bf16 g_nh[ROWS*DD];
__device__ bf16 g_nl[ROWS*DD];
__device__ bf16 g_vih[ROWS*DD];
__device__ bf16 g_vil[ROWS*DD];
__device__ bf16 g_wgh[DD*HH];
__device__ bf16 g_wgl[DD*HH];
__device__ bf16 g_wqh[DD*DD];
__device__ bf16 g_wql[DD*DD];
__device__ bf16 g_woh[HH*DD];
__device__ bf16 g_wol[HH*DD];
__device__ float g_gate[ROWS*HH];
__device__ bf16 g_vrh[ROWS*HH];
__device__ bf16 g_vrl[ROWS*HH];
__device__ bf16 g_vTh[HH*ROWS];
__device__ bf16 g_vTl[HH*ROWS];
__device__ bf16 g_qh[ROWS*DD];
__device__ bf16 g_ql[ROWS*DD];
__device__ bf16 g_kh[ROWS*DD];
__device__ bf16 g_kl[ROWS*DD];
__device__ bf16 g_avgh[ROWS*HH];
__device__ bf16 g_avgl[ROWS*HH];
__device__ bf16 g_atth[(size_t)ROWS*SS];      // 134 MB

// ================= PTX helpers (base ISA only) =================
__device__ __forceinline__ uint32_t smem_u32(const void* p) {
    uint32_t a;
    asm("{ .reg .u64 t; cvta.to.shared.u64 t, %1; cvt.u32.u64 %0, t; }" : "=r"(a) : "l"(p));
    return a;
}
__device__ __forceinline__ void cp16(uint32_t s, const void* g) {
    asm volatile("cp.async.cg.shared.global [%0], [%1], 16;" :: "r"(s), "l"(g) : "memory");
}
__device__ __forceinline__ void cp_commit() { asm volatile("cp.async.commit_group;" ::: "memory"); }
template<int N> __device__ __forceinline__ void cp_wait() {
    asm volatile("cp.async.wait_group %0;" :: "n"(N) : "memory");
}
__device__ __forceinline__ void ldm_x4(uint32_t &r0, uint32_t &r1, uint32_t &r2, uint32_t &r3, uint32_t a) {
    asm volatile("ldmatrix.sync.aligned.m8n8.x4.shared.b16 {%0,%1,%2,%3}, [%4];"
        : "=r"(r0), "=r"(r1), "=r"(r2), "=r"(r3) : "r"(a));
}
__device__ __forceinline__ void ldm_x2(uint32_t &r0, uint32_t &r1, uint32_t a) {
    asm volatile("ldmatrix.sync.aligned.m8n8.x2.shared.b16 {%0,%1}, [%2];"
        : "=r"(r0), "=r"(r1) : "r"(a));
}
__device__ __forceinline__ void mma16816(float (&c)[4], const uint32_t (&a)[4], const uint32_t (&b)[2]) {
    asm volatile("mma.sync.aligned.m16n8k16.row.col.f32.bf16.bf16.f32 "
        "{%0,%1,%2,%3}, {%4,%5,%6,%7}, {%8,%9}, {%0,%1,%2,%3};"
        : "+f"(c[0]), "+f"(c[1]), "+f"(c[2]), "+f"(c[3])
        : "r"(a[0]), "r"(a[1]), "r"(a[2]), "r"(a[3]), "r"(b[0]), "r"(b[1]));
}
__device__ __forceinline__ void ldsA(uint32_t (&a)[4], uint32_t base, int mrow, int kt, int lid) {
    int g = lid >> 3, r = lid & 7;
    int row = mrow + ((g & 1) << 3) + r;
    int ch = (kt << 1) + (g >> 1);
    ldm_x4(a[0], a[1], a[2], a[3], base + row * 128 + ((ch ^ (row & 7)) << 4));
}
__device__ __forceinline__ void ldsB(uint32_t (&b)[2], uint32_t base, int nrow, int kt, int lid) {
    int g = (lid >> 3) & 1, r = lid & 7;
    int row = nrow + r;
    int ch = (kt << 1) + g;
    ldm_x2(b[0], b[1], base + row * 128 + ((ch ^ (row & 7)) << 4));
}
// 512-thread tile loader: [NROWS x 64] bf16 k-contiguous -> swizzled smem
template<int NROWS>
__device__ __forceinline__ void load_tile64(uint32_t sbase, const bf16* g, size_t rstride, int tid) {
    #pragma unroll
    for (int i = 0; i < NROWS * 8; i += 512) {
        int idx = i + tid;
        int r = idx >> 3, c = idx & 7;
        cp16(sbase + r * 128 + ((c ^ (r & 7)) << 4), g + (size_t)r * rstride + c * 8);
    }
}
__device__ __forceinline__ float silu_f(float x) { return x / (1.0f + expf(-x)); }
__device__ __forceinline__ void split2(float x, bf16 &h, bf16 &l) {
    h = __float2bfloat16(x);
    l = __float2bfloat16(x - __bfloat162float(h));
}

// ================= kernel 1: rope + layernorm -> bf16 hi/lo =================
__global__ void prep_kernel(const float* __restrict__ q, const float* __restrict__ g,
                            const float* __restrict__ b,
                            bf16* __restrict__ nh, bf16* __restrict__ nl) {
    const int row = blockIdx.x;
    const int d = threadIdx.x;
    const int t = row & (SS - 1);
    float x = q[(size_t)row * DD + d];
    float y = x;
    if (d < 32) {
        int j = d >> 1;
        double dinv = pow(10000.0, -(double)j / 16.0);
        float f = (float)t * (float)dinv;
        float c = cosf(f), s = sinf(f);
        float partner = __shfl_xor_sync(0xffffffffu, x, 1);
        y = (d & 1) ? (x * c + partner * s) : (x * c - partner * s);
    }
    __shared__ float red[4];
    float v = y;
    #pragma unroll
    for (int o2 = 16; o2; o2 >>= 1) v += __shfl_xor_sync(0xffffffffu, v, o2);
    if ((threadIdx.x & 31) == 0) red[threadIdx.x >> 5] = v;
    __syncthreads();
    float mu = (red[0] + red[1] + red[2] + red[3]) * (1.0f / 128.0f);
    float dv = y - mu;
    float v2 = dv * dv;
    __syncthreads();
    #pragma unroll
    for (int o2 = 16; o2; o2 >>= 1) v2 += __shfl_xor_sync(0xffffffffu, v2, o2);
    if ((threadIdx.x & 31) == 0) red[threadIdx.x >> 5] = v2;
    __syncthreads();
    float var = (red[0] + red[1] + red[2] + red[3]) * (1.0f / 128.0f);
    float rs = rsqrtf(var + 1e-5f);
    float out = dv * rs * g[d] + b[d];
    bf16 h, l; split2(out, h, l);
    nh[(size_t)row * DD + d] = h;
    nl[(size_t)row * DD + d] = l;
}

// ================= elementwise f32 -> bf16 hi/lo split =================
__global__ void split_kernel(const float* __restrict__ x, bf16* __restrict__ xh,
                             bf16* __restrict__ xl, int n) {
    int i = blockIdx.x * 256 + threadIdx.x;
    if (i < n) {
        bf16 h, l; split2(x[i], h, l);
        xh[i] = h; xl[i] = l;
    }
}

// ================= all weights transpose+split in ONE launch =================
__global__ void wsplit_all(const float* __restrict__ Wg, const float* __restrict__ Wq,
                           const float* __restrict__ Wo,
                           bf16* __restrict__ wgh, bf16* __restrict__ wgl,
                           bf16* __restrict__ wqh, bf16* __restrict__ wql,
                           bf16* __restrict__ woh, bf16* __restrict__ wol) {
    int i = blockIdx.x * 256 + threadIdx.x;
    const float* W; bf16 *wh, *wl; int K, N, off;
    if (i < 32768)       { W = Wg; wh = wgh; wl = wgl; K = 128; N = 256; off = i; }
    else if (i < 49152)  { W = Wq; wh = wqh; wl = wql; K = 128; N = 128; off = i - 32768; }
    else if (i < 81920)  { W = Wo; wh = woh; wl = wol; K = 256; N = 128; off = i - 49152; }
    else return;
    int k = off / N, n = off % N;
    bf16 h, l; split2(W[(size_t)k * N + n], h, l);
    wh[(size_t)n * K + k] = h;
    wl[(size_t)n * K + k] = l;
}

// ================= bf16 transpose (hi & lo via z) =========================
__global__ void transpose2(const bf16* __restrict__ vh, const bf16* __restrict__ vl,
                           bf16* __restrict__ vth, bf16* __restrict__ vtl) {
    const bf16* in = blockIdx.z ? vl : vh;
    bf16* out = blockIdx.z ? vtl : vth;
    __shared__ bf16 tile[32][33];
    int x = blockIdx.x * 32 + threadIdx.x;
    int y = blockIdx.y * 32 + threadIdx.y;
    #pragma unroll
    for (int dy = 0; dy < 32; dy += 8)
        tile[threadIdx.y + dy][threadIdx.x] = in[(size_t)(y + dy) * HH + x];
    __syncthreads();
    int xo = blockIdx.y * 32 + threadIdx.x;
    int yo = blockIdx.x * 32 + threadIdx.y;
    #pragma unroll
    for (int dy = 0; dy < 32; dy += 8)
        out[(size_t)(yo + dy) * ROWS + xo] = tile[threadIdx.x][threadIdx.y + dy];
}

// ================= generic HMMA projection GEMM (512 thr, 16 warps) ========
#define MODE_GATE 0
#define MODE_V    1
#define MODE_QK   2
#define MODE_OUT  3

template<int NDIM, int KDIM, int MODE>
__global__ __launch_bounds__(512) void hmma_gemm(
    const bf16* __restrict__ Ah_g, const bf16* __restrict__ Al_g,
    const bf16* __restrict__ Bh_g, const bf16* __restrict__ Bl_g,
    const float* __restrict__ bias, const float* __restrict__ gam,
    const float* __restrict__ bet,
    float* __restrict__ O0f,
    bf16* __restrict__ qh, bf16* __restrict__ ql,
    bf16* __restrict__ kh, bf16* __restrict__ kl)
{
    constexpr int NSLAB = KDIM / 64;
    constexpr int BSTG = NDIM * 128;
    constexpr int STG = 32768 + 2 * BSTG;
    constexpr int NT = NDIM / 32;              // per-warp n-tiles (8 or 4)
    extern __shared__ __align__(128) char smem[];
    const uint32_t sb = smem_u32(smem);
    const int tid = threadIdx.x, wid = tid >> 5, lid = tid & 31;
    const int m0 = blockIdx.x * 128;
    const bf16* Ahp = Ah_g + (size_t)m0 * KDIM;
    const bf16* Alp = Al_g + (size_t)m0 * KDIM;

    const int wm = (wid >> 2) * 32;            // 4 m-warp groups of 32 rows
    const int wn = (wid & 3) * (NDIM / 4);
    float acc[2][NT][4];
    #pragma unroll
    for (int i = 0; i < 2; i++)
        #pragma unroll
        for (int j = 0; j < NT; j++)
            #pragma unroll
            for (int e = 0; e < 4; e++) acc[i][j][e] = 0.f;

    auto load_slab = [&](int s, uint32_t base) {
        load_tile64<128>(base,          Ahp + s * 64, KDIM, tid);
        load_tile64<128>(base + 16384,  Alp + s * 64, KDIM, tid);
        load_tile64<NDIM>(base + 32768, Bh_g + s * 64, KDIM, tid);
        load_tile64<NDIM>(base + 32768 + BSTG, Bl_g + s * 64, KDIM, tid);
        cp_commit();
    };
    auto compute = [&](uint32_t base) {
        const uint32_t Ah = base, Al = base + 16384;
        const uint32_t Bh = base + 32768, Bl = base + 32768 + BSTG;
        #pragma unroll
        for (int kt = 0; kt < 4; kt++) {
            uint32_t ah[2][4], al[2][4], bh[NT][2], bl[NT][2];
            #pragma unroll
            for (int mt = 0; mt < 2; mt++) ldsA(ah[mt], Ah, wm + mt*16, kt, lid);
            #pragma unroll
            for (int nt = 0; nt < NT; nt++) ldsB(bh[nt], Bh, wn + nt*8, kt, lid);
            #pragma unroll
            for (int mt = 0; mt < 2; mt++)
                #pragma unroll
                for (int nt = 0; nt < NT; nt++) mma16816(acc[mt][nt], ah[mt], bh[nt]);
            #pragma unroll
            for (int mt = 0; mt < 2; mt++) ldsA(al[mt], Al, wm + mt*16, kt, lid);
            #pragma unroll
            for (int mt = 0; mt < 2; mt++)
                #pragma unroll
                for (int nt = 0; nt < NT; nt++) mma16816(acc[mt][nt], al[mt], bh[nt]);
            #pragma unroll
            for (int nt = 0; nt < NT; nt++) ldsB(bl[nt], Bl, wn + nt*8, kt, lid);
            #pragma unroll
            for (int mt = 0; mt < 2; mt++)
                #pragma unroll
                for (int nt = 0; nt < NT; nt++) mma16816(acc[mt][nt], ah[mt], bl[nt]);
        }
    };

    load_slab(0, sb);
    if (NSLAB > 1) load_slab(1, sb + STG);
    #pragma unroll
    for (int j = 0; j < NSLAB; j++) {
        if (j + 1 < NSLAB) cp_wait<1>(); else cp_wait<0>();
        __syncthreads();
        compute(sb + (j & 1) * STG);
        if (j + 2 < NSLAB) { __syncthreads(); load_slab(j + 2, sb + (j & 1) * STG); }
    }

    const int lr = lid >> 2, lc = (lid & 3) * 2;
    #pragma unroll
    for (int mt = 0; mt < 2; mt++) {
        #pragma unroll
        for (int h2 = 0; h2 < 2; h2++) {
            const int row = m0 + wm + mt * 16 + h2 * 8 + lr;
            #pragma unroll
            for (int nt = 0; nt < NT; nt++) {
                const int col = wn + nt * 8 + lc;
                float x0 = acc[mt][nt][h2*2+0] + bias[col];
                float x1 = acc[mt][nt][h2*2+1] + bias[col+1];
                if (MODE == MODE_GATE) {
                    *(float2*)(O0f + (size_t)row * NDIM + col) = make_float2(silu_f(x0), silu_f(x1));
                } else if (MODE == MODE_V) {
                    bf162 hp, lp;
                    split2(silu_f(x0), hp.x, lp.x); split2(silu_f(x1), hp.y, lp.y);
                    *(bf162*)(qh + (size_t)row * NDIM + col) = hp;
                    *(bf162*)(ql + (size_t)row * NDIM + col) = lp;
                } else if (MODE == MODE_QK) {
                    float y0 = silu_f(x0), y1 = silu_f(x1);
                    float q0 = y0 * gam[col] + bet[col], q1 = y1 * gam[col+1] + bet[col+1];
                    float k0 = y0 * gam[NDIM+col] + bet[NDIM+col], k1 = y1 * gam[NDIM+col+1] + bet[NDIM+col+1];
                    bf162 hp, lp;
                    split2(q0, hp.x, lp.x); split2(q1, hp.y, lp.y);
                    *(bf162*)(qh + (size_t)row * NDIM + col) = hp;
                    *(bf162*)(ql + (size_t)row * NDIM + col) = lp;
                    split2(k0, hp.x, lp.x); split2(k1, hp.y, lp.y);
                    *(bf162*)(kh + (size_t)row * NDIM + col) = hp;
                    *(bf162*)(kl + (size_t)row * NDIM + col) = lp;
                } else {
                    *(float2*)(O0f + (size_t)row * NDIM + col) = make_float2(x0, x1);
                }
            }
        }
    }
}

// ================= big GEMM 1: att = relu(q@k^T/S)^2 (512 thr, 16 warps) ===
#define SIM_STG 98304   // Ah 16K | Al 16K | Bh 32K | Bl 32K
#define SIM_SMEM (2*SIM_STG)

__global__ __launch_bounds__(512) void sim_mma(
    const bf16* __restrict__ qh_g, const bf16* __restrict__ ql_g,
    const bf16* __restrict__ kh_g, const bf16* __restrict__ kl_g,
    float* __restrict__ att, bf16* __restrict__ atth)
{
    extern __shared__ __align__(128) char smem[];
    const uint32_t sb = smem_u32(smem);
    const int tid = threadIdx.x, wid = tid >> 5, lid = tid & 31;
    const int b = blockIdx.z, m0 = blockIdx.y * 128, n0 = blockIdx.x * 256;
    const bf16* qhp = qh_g + ((size_t)b * SS + m0) * DD;
    const bf16* qlp = ql_g + ((size_t)b * SS + m0) * DD;
    const bf16* khp = kh_g + ((size_t)b * SS + n0) * DD;
    const bf16* klp = kl_g + ((size_t)b * SS + n0) * DD;

    const int wm = (wid >> 2) * 32, wn = (wid & 3) * 64;
    float acc[2][8][4];
    #pragma unroll
    for (int i = 0; i < 2; i++)
        #pragma unroll
        for (int j = 0; j < 8; j++)
            #pragma unroll
            for (int e = 0; e < 4; e++) acc[i][j][e] = 0.f;

    auto load_half = [&](int h, uint32_t base) {
        load_tile64<128>(base,         qhp + h * 64, DD, tid);
        load_tile64<128>(base + 16384, qlp + h * 64, DD, tid);
        load_tile64<256>(base + 32768, khp + h * 64, DD, tid);
        load_tile64<256>(base + 65536, klp + h * 64, DD, tid);
        cp_commit();
    };
    auto compute = [&](uint32_t base) {
        const uint32_t Ah = base, Al = base + 16384, Bh = base + 32768, Bl = base + 65536;
        #pragma unroll
        for (int kt = 0; kt < 4; kt++) {
            uint32_t ah[2][4], al[2][4], bh[8][2], bl[8][2];
            #pragma unroll
            for (int mt = 0; mt < 2; mt++) ldsA(ah[mt], Ah, wm + mt*16, kt, lid);
            #pragma unroll
            for (int nt = 0; nt < 8; nt++) ldsB(bh[nt], Bh, wn + nt*8, kt, lid);
            #pragma unroll
            for (int mt = 0; mt < 2; mt++)
                #pragma unroll
                for (int nt = 0; nt < 8; nt++) mma16816(acc[mt][nt], ah[mt], bh[nt]);
            #pragma unroll
            for (int mt = 0; mt < 2; mt++) ldsA(al[mt], Al, wm + mt*16, kt, lid);
            #pragma unroll
            for (int mt = 0; mt < 2; mt++)
                #pragma unroll
                for (int nt = 0; nt < 8; nt++) mma16816(acc[mt][nt], al[mt], bh[nt]);
            #pragma unroll
            for (int nt = 0; nt < 8; nt++) ldsB(bl[nt], Bl, wn + nt*8, kt, lid);
            #pragma unroll
            for (int mt = 0; mt < 2; mt++)
                #pragma unroll
                for (int nt = 0; nt < 8; nt++) mma16816(acc[mt][nt], ah[mt], bl[nt]);
        }
    };

    load_half(0, sb);
    load_half(1, sb + SIM_STG);
    cp_wait<1>(); __syncthreads();
    compute(sb);
    cp_wait<0>(); __syncthreads();
    compute(sb + SIM_STG);

    const float invS = 1.0f / (float)SS;
    const int lr = lid >> 2, lc = (lid & 3) * 2;
    float* attb = att + (size_t)b * SS * SS;
    bf16* hib = atth + (size_t)b * SS * SS;
    #pragma unroll
    for (int mt = 0; mt < 2; mt++) {
        #pragma unroll
        for (int h2 = 0; h2 < 2; h2++) {
            int row = m0 + wm + mt * 16 + h2 * 8 + lr;
            size_t ro = (size_t)row * SS;
            #pragma unroll
            for (int nt = 0; nt < 8; nt++) {
                int col = n0 + wn + nt * 8 + lc;
                float s0 = fmaxf(acc[mt][nt][h2*2+0] * invS, 0.f);
                float s1 = fmaxf(acc[mt][nt][h2*2+1] * invS, 0.f);
                float a0 = s0 * s0, a1 = s1 * s1;
                *(float2*)(attb + ro + col) = make_float2(a0, a1);
                bf162 hp;
                hp.x = __float2bfloat16(a0); hp.y = __float2bfloat16(a1);
                *(bf162*)(hib + ro + col) = hp;
            }
        }
    }
}

// ================= big GEMM 2: av = atth @ (vh+vl), *gate (512 thr) ========
#define AT_STG 81920    // A 16K | vh 32K | vl 32K
#define AT_SMEM (2*AT_STG)
#define AT_NS 64

__global__ __launch_bounds__(512) void attnv_mma(
    const bf16* __restrict__ atth,
    const bf16* __restrict__ vth, const bf16* __restrict__ vtl,
    const float* __restrict__ gate,
    bf16* __restrict__ avgh, bf16* __restrict__ avgl)
{
    extern __shared__ __align__(128) char smem[];
    const uint32_t sb = smem_u32(smem);
    const int tid = threadIdx.x, wid = tid >> 5, lid = tid & 31;
    const int b = blockIdx.y, m0 = blockIdx.x * 128;
    const bf16* ahp = atth + (size_t)b * SS * SS + (size_t)m0 * SS;
    const bf16* vhp = vth + (size_t)b * SS;
    const bf16* vlp = vtl + (size_t)b * SS;

    const int wm = (wid >> 2) * 32, wn = (wid & 3) * 64;
    float acc[2][8][4];
    #pragma unroll
    for (int i = 0; i < 2; i++)
        #pragma unroll
        for (int j = 0; j < 8; j++)
            #pragma unroll
            for (int e = 0; e < 4; e++) acc[i][j][e] = 0.f;

    auto load_slab = [&](int j, int s) {
        uint32_t base = sb + s * AT_STG;
        load_tile64<128>(base,         ahp + j * 64, SS, tid);
        load_tile64<256>(base + 16384, vhp + j * 64, ROWS, tid);
        load_tile64<256>(base + 49152, vlp + j * 64, ROWS, tid);
        cp_commit();
    };
    auto compute = [&](int s) {
        uint32_t base = sb + s * AT_STG;
        const uint32_t Aa = base, Bh = base + 16384, Bl = base + 49152;
        #pragma unroll
        for (int kt = 0; kt < 4; kt++) {
            uint32_t af[2][4], bhf[8][2], blf[8][2];
            #pragma unroll
            for (int mt = 0; mt < 2; mt++) ldsA(af[mt], Aa, wm + mt*16, kt, lid);
            #pragma unroll
            for (int nt = 0; nt < 8; nt++) ldsB(bhf[nt], Bh, wn + nt*8, kt, lid);
            #pragma unroll
            for (int mt = 0; mt < 2; mt++)
                #pragma unroll
                for (int nt = 0; nt < 8; nt++) mma16816(acc[mt][nt], af[mt], bhf[nt]);
            #pragma unroll
            for (int nt = 0; nt < 8; nt++) ldsB(blf[nt], Bl, wn + nt*8, kt, lid);
            #pragma unroll
            for (int mt = 0; mt < 2; mt++)
                #pragma unroll
                for (int nt = 0; nt < 8; nt++) mma16816(acc[mt][nt], af[mt], blf[nt]);
        }
    };

    load_slab(0, 0);
    load_slab(1, 1);
    for (int j = 0; j < AT_NS; j++) {
        if (j + 1 < AT_NS) cp_wait<1>(); else cp_wait<0>();
        __syncthreads();
        compute(j & 1);
        if (j + 2 < AT_NS) { __syncthreads(); load_slab(j + 2, j & 1); }
    }

    const int lr = lid >> 2, lc = (lid & 3) * 2;
    #pragma unroll
    for (int mt = 0; mt < 2; mt++) {
        #pragma unroll
        for (int h2 = 0; h2 < 2; h2++) {
            size_t grow = (size_t)b * SS + m0 + wm + mt * 16 + h2 * 8 + lr;
            const float* gp = gate + grow * HH;
            bf16* hp_ = avgh + grow * HH;
            bf16* lp_ = avgl + grow * HH;
            #pragma unroll
            for (int nt = 0; nt < 8; nt++) {
                int col = wn + nt * 8 + lc;
                float2 g2 = *(const float2*)(gp + col);
                float o0 = acc[mt][nt][h2*2+0] * g2.x;
                float o1 = acc[mt][nt][h2*2+1] * g2.y;
                bf162 hh, ll;
                split2(o0, hh.x, ll.x); split2(o1, hh.y, ll.y);
                *(bf162*)(hp_ + col) = hh;
                *(bf162*)(lp_ + col) = ll;
            }
        }
    }
}

// ================= launch =================
extern "C" void kernel_launch(void* const* d_in, const int* in_sizes, int n_in,
                              void* d_out, int out_size)
{
    const float* query  = (const float*)d_in[0];
    const float* value  = (const float*)d_in[2];
    const float* ln_g   = (const float*)d_in[3];
    const float* ln_b   = (const float*)d_in[4];
    const float* W_gate = (const float*)d_in[5];
    const float* b_gate = (const float*)d_in[6];
    const float* W_qk   = (const float*)d_in[7];
    const float* b_qk   = (const float*)d_in[8];
    const float* os_g   = (const float*)d_in[9];
    const float* os_b   = (const float*)d_in[10];
    const float* W_out  = (const float*)d_in[11];
    const float* b_out  = (const float*)d_in[12];

    float* out = (float*)d_out;
    float* att = out + (size_t)ROWS * DD;

    bf16 *p_nh, *p_nl, *p_vih, *p_vil, *p_wgh, *p_wgl, *p_wqh, *p_wql, *p_woh, *p_wol;
    bf16 *p_vrh, *p_vrl, *p_vTh, *p_vTl, *p_qh, *p_ql, *p_kh, *p_kl, *p_avgh, *p_avgl, *p_atth;
    float *p_gate;
    cudaGetSymbolAddress((void**)&p_nh, g_nh);
    cudaGetSymbolAddress((void**)&p_nl, g_nl);
    cudaGetSymbolAddress((void**)&p_vih, g_vih);
    cudaGetSymbolAddress((void**)&p_vil, g_vil);
    cudaGetSymbolAddress((void**)&p_wgh, g_wgh);
    cudaGetSymbolAddress((void**)&p_wgl, g_wgl);
    cudaGetSymbolAddress((void**)&p_wqh, g_wqh);
    cudaGetSymbolAddress((void**)&p_wql, g_wql);
    cudaGetSymbolAddress((void**)&p_woh, g_woh);
    cudaGetSymbolAddress((void**)&p_wol, g_wol);
    cudaGetSymbolAddress((void**)&p_gate, g_gate);
    cudaGetSymbolAddress((void**)&p_vrh, g_vrh);
    cudaGetSymbolAddress((void**)&p_vrl, g_vrl);
    cudaGetSymbolAddress((void**)&p_vTh, g_vTh);
    cudaGetSymbolAddress((void**)&p_vTl, g_vTl);
    cudaGetSymbolAddress((void**)&p_qh, g_qh);
    cudaGetSymbolAddress((void**)&p_ql, g_ql);
    cudaGetSymbolAddress((void**)&p_kh, g_kh);
    cudaGetSymbolAddress((void**)&p_kl, g_kl);
    cudaGetSymbolAddress((void**)&p_avgh, g_avgh);
    cudaGetSymbolAddress((void**)&p_avgl, g_avgl);
    cudaGetSymbolAddress((void**)&p_atth, g_atth);

    cudaFuncSetAttribute(sim_mma,  cudaFuncAttributeMaxDynamicSharedMemorySize, SIM_SMEM);
    cudaFuncSetAttribute(attnv_mma, cudaFuncAttributeMaxDynamicSharedMemorySize, AT_SMEM);
    cudaFuncSetAttribute((const void*)hmma_gemm<256,128,MODE_GATE>, cudaFuncAttributeMaxDynamicSharedMemorySize, 2*(32768+2*256*128));
    cudaFuncSetAttribute((const void*)hmma_gemm<256,128,MODE_V>,    cudaFuncAttributeMaxDynamicSharedMemorySize, 2*(32768+2*256*128));
    cudaFuncSetAttribute((const void*)hmma_gemm<128,128,MODE_QK>,   cudaFuncAttributeMaxDynamicSharedMemorySize, 2*(32768+2*128*128));
    cudaFuncSetAttribute((const void*)hmma_gemm<128,256,MODE_OUT>,  cudaFuncAttributeMaxDynamicSharedMemorySize, 2*(32768+2*128*128));

    // prep + splits
    prep_kernel<<<ROWS, 128>>>(query, ln_g, ln_b, p_nh, p_nl);
    split_kernel<<<(ROWS*DD + 255)/256, 256>>>(value, p_vih, p_vil, ROWS*DD);
    wsplit_all<<<320, 256>>>(W_gate, W_qk, W_out, p_wgh, p_wgl, p_wqh, p_wql, p_woh, p_wol);

    // projections (HMMA)
    hmma_gemm<256,128,MODE_GATE><<<128, 512, 2*(32768+2*256*128)>>>(
        p_nh, p_nl, p_wgh, p_wgl, b_gate, nullptr, nullptr,
        p_gate, nullptr, nullptr, nullptr, nullptr);
    hmma_gemm<256,128,MODE_V><<<128, 512, 2*(32768+2*256*128)>>>(
        p_vih, p_vil, p_wgh, p_wgl, b_gate, nullptr, nullptr,
        nullptr, p_vrh, p_vrl, nullptr, nullptr);
    hmma_gemm<128,128,MODE_QK><<<128, 512, 2*(32768+2*128*128)>>>(
        p_nh, p_nl, p_wqh, p_wql, b_qk, os_g, os_b,
        nullptr, p_qh, p_ql, p_kh, p_kl);
    transpose2<<<dim3(HH/32, ROWS/32, 2), dim3(32, 8)>>>(p_vrh, p_vrl, p_vTh, p_vTl);

    // attention
    sim_mma<<<dim3(SS/256, SS/128, BB), 512, SIM_SMEM>>>(p_qh, p_ql, p_kh, p_kl,
        att, p_atth);
    attnv_mma<<<dim3(SS/128, BB), 512, AT_SMEM>>>(p_atth, p_vTh, p_vTl, p_gate,
        p_avgh, p_avgl);

    // output projection
    hmma_gemm<128,256,MODE_OUT><<<128, 512, 2*(32768+2*128*128)>>>(
        p_avgh, p_avgl, p_woh, p_wol, b_out, nullptr, nullptr,
        out, nullptr, nullptr, nullptr, nullptr);
}

// round 9
// speedup vs baseline: 1.2057x; 1.2057x over previous
#include <cuda_runtime.h>
#include <cuda_fp16.h>
#include <math.h>
#include <stdint.h>

#define BB 4
#define SS 4096
#define DD 128
#define HH 256
#define ROWS (BB*SS)   // 16384
#define INV_S2 (1.0f/16777216.0f)   // 2^-24, exact

typedef __half f16;
typedef __half2 f162;

// ---------------- scratch (no allocations allowed) ----------------
__device__ f16 g_nh[ROWS*DD];
__device__ f16 g_nl[ROWS*DD];
__device__ f16 g_vih[ROWS*DD];
__device__ f16 g_vil[ROWS*DD];
__device__ f16 g_wgh[DD*HH];
__device__ f16 g_wgl[DD*HH];
__device__ f16 g_wqh[DD*DD];
__device__ f16 g_wql[DD*DD];
__device__ f16 g_woh[HH*DD];
__device__ f16 g_wol[HH*DD];
__device__ float g_gate[ROWS*HH];
__device__ f16 g_vr[ROWS*HH];                 // v fp16 [seq][256]
__device__ f16 g_vT[HH*ROWS];                 // v^T fp16 [256][16384]
__device__ f16 g_qh[ROWS*DD];
__device__ f16 g_ql[ROWS*DD];
__device__ f16 g_kh[ROWS*DD];
__device__ f16 g_kl[ROWS*DD];
__device__ f16 g_avgh[ROWS*HH];               // scaled by 2^24
__device__ f16 g_avgl[ROWS*HH];
__device__ f16 g_atth[(size_t)ROWS*SS];       // att scaled by 2^24 (fp16)

// ================= PTX helpers (base ISA only) =================
__device__ __forceinline__ uint32_t smem_u32(const void* p) {
    uint32_t a;
    asm("{ .reg .u64 t; cvta.to.shared.u64 t, %1; cvt.u32.u64 %0, t; }" : "=r"(a) : "l"(p));
    return a;
}
__device__ __forceinline__ void cp16(uint32_t s, const void* g) {
    asm volatile("cp.async.cg.shared.global [%0], [%1], 16;" :: "r"(s), "l"(g) : "memory");
}
__device__ __forceinline__ void cp_commit() { asm volatile("cp.async.commit_group;" ::: "memory"); }
template<int N> __device__ __forceinline__ void cp_wait() {
    asm volatile("cp.async.wait_group %0;" :: "n"(N) : "memory");
}
__device__ __forceinline__ void ldm_x4(uint32_t &r0, uint32_t &r1, uint32_t &r2, uint32_t &r3, uint32_t a) {
    asm volatile("ldmatrix.sync.aligned.m8n8.x4.shared.b16 {%0,%1,%2,%3}, [%4];"
        : "=r"(r0), "=r"(r1), "=r"(r2), "=r"(r3) : "r"(a));
}
__device__ __forceinline__ void ldm_x2(uint32_t &r0, uint32_t &r1, uint32_t a) {
    asm volatile("ldmatrix.sync.aligned.m8n8.x2.shared.b16 {%0,%1}, [%2];"
        : "=r"(r0), "=r"(r1) : "r"(a));
}
__device__ __forceinline__ void mma16816(float (&c)[4], const uint32_t (&a)[4], const uint32_t (&b)[2]) {
    asm volatile("mma.sync.aligned.m16n8k16.row.col.f32.f16.f16.f32 "
        "{%0,%1,%2,%3}, {%4,%5,%6,%7}, {%8,%9}, {%0,%1,%2,%3};"
        : "+f"(c[0]), "+f"(c[1]), "+f"(c[2]), "+f"(c[3])
        : "r"(a[0]), "r"(a[1]), "r"(a[2]), "r"(a[3]), "r"(b[0]), "r"(b[1]));
}
__device__ __forceinline__ void ldsA(uint32_t (&a)[4], uint32_t base, int mrow, int kt, int lid) {
    int g = lid >> 3, r = lid & 7;
    int row = mrow + ((g & 1) << 3) + r;
    int ch = (kt << 1) + (g >> 1);
    ldm_x4(a[0], a[1], a[2], a[3], base + row * 128 + ((ch ^ (row & 7)) << 4));
}
__device__ __forceinline__ void ldsB(uint32_t (&b)[2], uint32_t base, int nrow, int kt, int lid) {
    int g = (lid >> 3) & 1, r = lid & 7;
    int row = nrow + r;
    int ch = (kt << 1) + g;
    ldm_x2(b[0], b[1], base + row * 128 + ((ch ^ (row & 7)) << 4));
}
// 512-thread tile loader: [NROWS x 64] f16 k-contiguous -> swizzled smem
template<int NROWS>
__device__ __forceinline__ void load_tile64(uint32_t sbase, const f16* g, size_t rstride, int tid) {
    #pragma unroll
    for (int i = 0; i < NROWS * 8; i += 512) {
        int idx = i + tid;
        int r = idx >> 3, c = idx & 7;
        cp16(sbase + r * 128 + ((c ^ (r & 7)) << 4), g + (size_t)r * rstride + c * 8);
    }
}
__device__ __forceinline__ float silu_f(float x) { return x / (1.0f + expf(-x)); }
__device__ __forceinline__ void split2(float x, f16 &h, f16 &l) {
    h = __float2half_rn(x);
    l = __float2half_rn(x - __half2float(h));
}

// ================= kernel 1: rope + layernorm -> fp16 hi/lo =================
__global__ void prep_kernel(const float* __restrict__ q, const float* __restrict__ g,
                            const float* __restrict__ b,
                            f16* __restrict__ nh, f16* __restrict__ nl) {
    const int row = blockIdx.x;
    const int d = threadIdx.x;
    const int t = row & (SS - 1);
    float x = q[(size_t)row * DD + d];
    float y = x;
    if (d < 32) {
        int j = d >> 1;
        double dinv = pow(10000.0, -(double)j / 16.0);
        float f = (float)t * (float)dinv;
        float c = cosf(f), s = sinf(f);
        float partner = __shfl_xor_sync(0xffffffffu, x, 1);
        y = (d & 1) ? (x * c + partner * s) : (x * c - partner * s);
    }
    __shared__ float red[4];
    float v = y;
    #pragma unroll
    for (int o2 = 16; o2; o2 >>= 1) v += __shfl_xor_sync(0xffffffffu, v, o2);
    if ((threadIdx.x & 31) == 0) red[threadIdx.x >> 5] = v;
    __syncthreads();
    float mu = (red[0] + red[1] + red[2] + red[3]) * (1.0f / 128.0f);
    float dv = y - mu;
    float v2 = dv * dv;
    __syncthreads();
    #pragma unroll
    for (int o2 = 16; o2; o2 >>= 1) v2 += __shfl_xor_sync(0xffffffffu, v2, o2);
    if ((threadIdx.x & 31) == 0) red[threadIdx.x >> 5] = v2;
    __syncthreads();
    float var = (red[0] + red[1] + red[2] + red[3]) * (1.0f / 128.0f);
    float rs = rsqrtf(var + 1e-5f);
    float out = dv * rs * g[d] + b[d];
    f16 h, l; split2(out, h, l);
    nh[(size_t)row * DD + d] = h;
    nl[(size_t)row * DD + d] = l;
}

// ================= elementwise f32 -> fp16 hi/lo split =================
__global__ void split_kernel(const float* __restrict__ x, f16* __restrict__ xh,
                             f16* __restrict__ xl, int n) {
    int i = blockIdx.x * 256 + threadIdx.x;
    if (i < n) {
        f16 h, l; split2(x[i], h, l);
        xh[i] = h; xl[i] = l;
    }
}

// ================= all weights transpose+split in ONE launch =================
__global__ void wsplit_all(const float* __restrict__ Wg, const float* __restrict__ Wq,
                           const float* __restrict__ Wo,
                           f16* __restrict__ wgh, f16* __restrict__ wgl,
                           f16* __restrict__ wqh, f16* __restrict__ wql,
                           f16* __restrict__ woh, f16* __restrict__ wol) {
    int i = blockIdx.x * 256 + threadIdx.x;
    const float* W; f16 *wh, *wl; int K, N, off;
    if (i < 32768)       { W = Wg; wh = wgh; wl = wgl; K = 128; N = 256; off = i; }
    else if (i < 49152)  { W = Wq; wh = wqh; wl = wql; K = 128; N = 128; off = i - 32768; }
    else if (i < 81920)  { W = Wo; wh = woh; wl = wol; K = 256; N = 128; off = i - 49152; }
    else return;
    int k = off / N, n = off % N;
    f16 h, l; split2(W[(size_t)k * N + n], h, l);
    wh[(size_t)n * K + k] = h;
    wl[(size_t)n * K + k] = l;
}

// ================= fp16 transpose: [16384][256] -> [256][16384] ============
__global__ void transpose_f16(const f16* __restrict__ v, f16* __restrict__ vt) {
    __shared__ f16 tile[32][33];
    int x = blockIdx.x * 32 + threadIdx.x;
    int y = blockIdx.y * 32 + threadIdx.y;
    #pragma unroll
    for (int dy = 0; dy < 32; dy += 8)
        tile[threadIdx.y + dy][threadIdx.x] = v[(size_t)(y + dy) * HH + x];
    __syncthreads();
    int xo = blockIdx.y * 32 + threadIdx.x;
    int yo = blockIdx.x * 32 + threadIdx.y;
    #pragma unroll
    for (int dy = 0; dy < 32; dy += 8)
        vt[(size_t)(yo + dy) * ROWS + xo] = tile[threadIdx.x][threadIdx.y + dy];
}

// ================= generic HMMA projection GEMM (512 thr, 16 warps) ========
#define MODE_GATE 0
#define MODE_V    1
#define MODE_QK   2
#define MODE_OUT  3   // acc is scaled by 2^24; multiply by INV_S2 before bias

template<int NDIM, int KDIM, int MODE>
__global__ __launch_bounds__(512) void hmma_gemm(
    const f16* __restrict__ Ah_g, const f16* __restrict__ Al_g,
    const f16* __restrict__ Bh_g, const f16* __restrict__ Bl_g,
    const float* __restrict__ bias, const float* __restrict__ gam,
    const float* __restrict__ bet,
    float* __restrict__ O0f, f16* __restrict__ O0h,
    f16* __restrict__ qh, f16* __restrict__ ql,
    f16* __restrict__ kh, f16* __restrict__ kl)
{
    constexpr int NSLAB = KDIM / 64;
    constexpr int BSTG = NDIM * 128;
    constexpr int STG = 32768 + 2 * BSTG;
    constexpr int NT = NDIM / 32;
    extern __shared__ __align__(128) char smem[];
    const uint32_t sb = smem_u32(smem);
    const int tid = threadIdx.x, wid = tid >> 5, lid = tid & 31;
    const int m0 = blockIdx.x * 128;
    const f16* Ahp = Ah_g + (size_t)m0 * KDIM;
    const f16* Alp = Al_g + (size_t)m0 * KDIM;

    const int wm = (wid >> 2) * 32;
    const int wn = (wid & 3) * (NDIM / 4);
    float acc[2][NT][4];
    #pragma unroll
    for (int i = 0; i < 2; i++)
        #pragma unroll
        for (int j = 0; j < NT; j++)
            #pragma unroll
            for (int e = 0; e < 4; e++) acc[i][j][e] = 0.f;

    auto load_slab = [&](int s, uint32_t base) {
        load_tile64<128>(base,          Ahp + s * 64, KDIM, tid);
        load_tile64<128>(base + 16384,  Alp + s * 64, KDIM, tid);
        load_tile64<NDIM>(base + 32768, Bh_g + s * 64, KDIM, tid);
        load_tile64<NDIM>(base + 32768 + BSTG, Bl_g + s * 64, KDIM, tid);
        cp_commit();
    };
    auto compute = [&](uint32_t base) {
        const uint32_t Ah = base, Al = base + 16384;
        const uint32_t Bh = base + 32768, Bl = base + 32768 + BSTG;
        #pragma unroll
        for (int kt = 0; kt < 4; kt++) {
            uint32_t ah[2][4], al[2][4], bh[NT][2], bl[NT][2];
            #pragma unroll
            for (int mt = 0; mt < 2; mt++) ldsA(ah[mt], Ah, wm + mt*16, kt, lid);
            #pragma unroll
            for (int nt = 0; nt < NT; nt++) ldsB(bh[nt], Bh, wn + nt*8, kt, lid);
            #pragma unroll
            for (int mt = 0; mt < 2; mt++)
                #pragma unroll
                for (int nt = 0; nt < NT; nt++) mma16816(acc[mt][nt], ah[mt], bh[nt]);
            #pragma unroll
            for (int mt = 0; mt < 2; mt++) ldsA(al[mt], Al, wm + mt*16, kt, lid);
            #pragma unroll
            for (int mt = 0; mt < 2; mt++)
                #pragma unroll
                for (int nt = 0; nt < NT; nt++) mma16816(acc[mt][nt], al[mt], bh[nt]);
            #pragma unroll
            for (int nt = 0; nt < NT; nt++) ldsB(bl[nt], Bl, wn + nt*8, kt, lid);
            #pragma unroll
            for (int mt = 0; mt < 2; mt++)
                #pragma unroll
                for (int nt = 0; nt < NT; nt++) mma16816(acc[mt][nt], ah[mt], bl[nt]);
        }
    };

    load_slab(0, sb);
    if (NSLAB > 1) load_slab(1, sb + STG);
    #pragma unroll
    for (int j = 0; j < NSLAB; j++) {
        if (j + 1 < NSLAB) cp_wait<1>(); else cp_wait<0>();
        __syncthreads();
        compute(sb + (j & 1) * STG);
        if (j + 2 < NSLAB) { __syncthreads(); load_slab(j + 2, sb + (j & 1) * STG); }
    }

    const float scl = (MODE == MODE_OUT) ? INV_S2 : 1.0f;
    const int lr = lid >> 2, lc = (lid & 3) * 2;
    #pragma unroll
    for (int mt = 0; mt < 2; mt++) {
        #pragma unroll
        for (int h2 = 0; h2 < 2; h2++) {
            const int row = m0 + wm + mt * 16 + h2 * 8 + lr;
            #pragma unroll
            for (int nt = 0; nt < NT; nt++) {
                const int col = wn + nt * 8 + lc;
                float x0 = acc[mt][nt][h2*2+0] * scl + bias[col];
                float x1 = acc[mt][nt][h2*2+1] * scl + bias[col+1];
                if (MODE == MODE_GATE) {
                    *(float2*)(O0f + (size_t)row * NDIM + col) = make_float2(silu_f(x0), silu_f(x1));
                } else if (MODE == MODE_V) {
                    f162 p;
                    p.x = __float2half_rn(silu_f(x0)); p.y = __float2half_rn(silu_f(x1));
                    *(f162*)(O0h + (size_t)row * NDIM + col) = p;
                } else if (MODE == MODE_QK) {
                    float y0 = silu_f(x0), y1 = silu_f(x1);
                    float q0 = y0 * gam[col] + bet[col], q1 = y1 * gam[col+1] + bet[col+1];
                    float k0 = y0 * gam[NDIM+col] + bet[NDIM+col], k1 = y1 * gam[NDIM+col+1] + bet[NDIM+col+1];
                    f162 hp, lp;
                    split2(q0, hp.x, lp.x); split2(q1, hp.y, lp.y);
                    *(f162*)(qh + (size_t)row * NDIM + col) = hp;
                    *(f162*)(ql + (size_t)row * NDIM + col) = lp;
                    split2(k0, hp.x, lp.x); split2(k1, hp.y, lp.y);
                    *(f162*)(kh + (size_t)row * NDIM + col) = hp;
                    *(f162*)(kl + (size_t)row * NDIM + col) = lp;
                } else {
                    *(float2*)(O0f + (size_t)row * NDIM + col) = make_float2(x0, x1);
                }
            }
        }
    }
}

// ================= big GEMM 1: att = relu(q@k^T/S)^2 (fp16 3-pass) =========
// atth stores relu(q@k^T)^2 (att scaled by 2^24); f32 att gets * 2^-24.
#define SIM_STG 98304   // Ah 16K | Al 16K | Bh 32K | Bl 32K
#define SIM_SMEM (2*SIM_STG)

__global__ __launch_bounds__(512) void sim_mma(
    const f16* __restrict__ qh_g, const f16* __restrict__ ql_g,
    const f16* __restrict__ kh_g, const f16* __restrict__ kl_g,
    float* __restrict__ att, f16* __restrict__ atth)
{
    extern __shared__ __align__(128) char smem[];
    const uint32_t sb = smem_u32(smem);
    const int tid = threadIdx.x, wid = tid >> 5, lid = tid & 31;
    const int b = blockIdx.z, m0 = blockIdx.y * 128, n0 = blockIdx.x * 256;
    const f16* qhp = qh_g + ((size_t)b * SS + m0) * DD;
    const f16* qlp = ql_g + ((size_t)b * SS + m0) * DD;
    const f16* khp = kh_g + ((size_t)b * SS + n0) * DD;
    const f16* klp = kl_g + ((size_t)b * SS + n0) * DD;

    const int wm = (wid >> 2) * 32, wn = (wid & 3) * 64;
    float acc[2][8][4];
    #pragma unroll
    for (int i = 0; i < 2; i++)
        #pragma unroll
        for (int j = 0; j < 8; j++)
            #pragma unroll
            for (int e = 0; e < 4; e++) acc[i][j][e] = 0.f;

    auto load_half = [&](int h, uint32_t base) {
        load_tile64<128>(base,         qhp + h * 64, DD, tid);
        load_tile64<128>(base + 16384, qlp + h * 64, DD, tid);
        load_tile64<256>(base + 32768, khp + h * 64, DD, tid);
        load_tile64<256>(base + 65536, klp + h * 64, DD, tid);
        cp_commit();
    };
    auto compute = [&](uint32_t base) {
        const uint32_t Ah = base, Al = base + 16384, Bh = base + 32768, Bl = base + 65536;
        #pragma unroll
        for (int kt = 0; kt < 4; kt++) {
            uint32_t ah[2][4], al[2][4], bh[8][2], bl[8][2];
            #pragma unroll
            for (int mt = 0; mt < 2; mt++) ldsA(ah[mt], Ah, wm + mt*16, kt, lid);
            #pragma unroll
            for (int nt = 0; nt < 8; nt++) ldsB(bh[nt], Bh, wn + nt*8, kt, lid);
            #pragma unroll
            for (int mt = 0; mt < 2; mt++)
                #pragma unroll
                for (int nt = 0; nt < 8; nt++) mma16816(acc[mt][nt], ah[mt], bh[nt]);
            #pragma unroll
            for (int mt = 0; mt < 2; mt++) ldsA(al[mt], Al, wm + mt*16, kt, lid);
            #pragma unroll
            for (int mt = 0; mt < 2; mt++)
                #pragma unroll
                for (int nt = 0; nt < 8; nt++) mma16816(acc[mt][nt], al[mt], bh[nt]);
            #pragma unroll
            for (int nt = 0; nt < 8; nt++) ldsB(bl[nt], Bl, wn + nt*8, kt, lid);
            #pragma unroll
            for (int mt = 0; mt < 2; mt++)
                #pragma unroll
                for (int nt = 0; nt < 8; nt++) mma16816(acc[mt][nt], ah[mt], bl[nt]);
        }
    };

    load_half(0, sb);
    load_half(1, sb + SIM_STG);
    cp_wait<1>(); __syncthreads();
    compute(sb);
    cp_wait<0>(); __syncthreads();
    compute(sb + SIM_STG);

    const int lr = lid >> 2, lc = (lid & 3) * 2;
    float* attb = att + (size_t)b * SS * SS;
    f16* hib = atth + (size_t)b * SS * SS;
    #pragma unroll
    for (int mt = 0; mt < 2; mt++) {
        #pragma unroll
        for (int h2 = 0; h2 < 2; h2++) {
            int row = m0 + wm + mt * 16 + h2 * 8 + lr;
            size_t ro = (size_t)row * SS;
            #pragma unroll
            for (int nt = 0; nt < 8; nt++) {
                int col = n0 + wn + nt * 8 + lc;
                float p0 = fmaxf(acc[mt][nt][h2*2+0], 0.f);
                float p1 = fmaxf(acc[mt][nt][h2*2+1], 0.f);
                float sa0 = p0 * p0, sa1 = p1 * p1;        // att * 2^24
                *(float2*)(attb + ro + col) = make_float2(sa0 * INV_S2, sa1 * INV_S2);
                f162 hp;
                hp.x = __float2half_rn(sa0); hp.y = __float2half_rn(sa1);
                *(f162*)(hib + ro + col) = hp;
            }
        }
    }
}

// ================= big GEMM 2: av = atth @ vT (fp16 1-pass), *gate =========
// acc is scaled by 2^24; avgh/avgl stored scaled (descaled in MODE_OUT).
#define AT_STG 49152    // A 16K | v 32K
#define AT_SMEM (3*AT_STG)
#define AT_NS 64

__global__ __launch_bounds__(512) void attnv_mma(
    const f16* __restrict__ atth, const f16* __restrict__ vt,
    const float* __restrict__ gate,
    f16* __restrict__ avgh, f16* __restrict__ avgl)
{
    extern __shared__ __align__(128) char smem[];
    const uint32_t sb = smem_u32(smem);
    const int tid = threadIdx.x, wid = tid >> 5, lid = tid & 31;
    const int b = blockIdx.y, m0 = blockIdx.x * 128;
    const f16* ahp = atth + (size_t)b * SS * SS + (size_t)m0 * SS;
    const f16* vp  = vt + (size_t)b * SS;

    const int wm = (wid >> 2) * 32, wn = (wid & 3) * 64;
    float acc[2][8][4];
    #pragma unroll
    for (int i = 0; i < 2; i++)
        #pragma unroll
        for (int j = 0; j < 8; j++)
            #pragma unroll
            for (int e = 0; e < 4; e++) acc[i][j][e] = 0.f;

    auto load_slab = [&](int j, int s) {
        uint32_t base = sb + s * AT_STG;
        load_tile64<128>(base,         ahp + j * 64, SS, tid);
        load_tile64<256>(base + 16384, vp + j * 64, ROWS, tid);
        cp_commit();
    };
    auto compute = [&](int s) {
        uint32_t base = sb + s * AT_STG;
        const uint32_t Aa = base, Bv = base + 16384;
        #pragma unroll
        for (int kt = 0; kt < 4; kt++) {
            uint32_t af[2][4], bf[8][2];
            #pragma unroll
            for (int mt = 0; mt < 2; mt++) ldsA(af[mt], Aa, wm + mt*16, kt, lid);
            #pragma unroll
            for (int nt = 0; nt < 8; nt++) ldsB(bf[nt], Bv, wn + nt*8, kt, lid);
            #pragma unroll
            for (int mt = 0; mt < 2; mt++)
                #pragma unroll
                for (int nt = 0; nt < 8; nt++) mma16816(acc[mt][nt], af[mt], bf[nt]);
        }
    };

    load_slab(0, 0);
    load_slab(1, 1);
    for (int j = 0; j < AT_NS; j++) {
        if (j + 1 < AT_NS) cp_wait<1>(); else cp_wait<0>();
        __syncthreads();
        if (j + 2 < AT_NS) load_slab(j + 2, (j + 2) % 3);
        compute(j % 3);
    }

    const int lr = lid >> 2, lc = (lid & 3) * 2;
    #pragma unroll
    for (int mt = 0; mt < 2; mt++) {
        #pragma unroll
        for (int h2 = 0; h2 < 2; h2++) {
            size_t grow = (size_t)b * SS + m0 + wm + mt * 16 + h2 * 8 + lr;
            const float* gp = gate + grow * HH;
            f16* hp_ = avgh + grow * HH;
            f16* lp_ = avgl + grow * HH;
            #pragma unroll
            for (int nt = 0; nt < 8; nt++) {
                int col = wn + nt * 8 + lc;
                float2 g2 = *(const float2*)(gp + col);
                float o0 = acc[mt][nt][h2*2+0] * g2.x;   // scaled by 2^24
                float o1 = acc[mt][nt][h2*2+1] * g2.y;
                f162 hh, ll;
                split2(o0, hh.x, ll.x); split2(o1, hh.y, ll.y);
                *(f162*)(hp_ + col) = hh;
                *(f162*)(lp_ + col) = ll;
            }
        }
    }
}

// ================= launch =================
extern "C" void kernel_launch(void* const* d_in, const int* in_sizes, int n_in,
                              void* d_out, int out_size)
{
    const float* query  = (const float*)d_in[0];
    const float* value  = (const float*)d_in[2];
    const float* ln_g   = (const float*)d_in[3];
    const float* ln_b   = (const float*)d_in[4];
    const float* W_gate = (const float*)d_in[5];
    const float* b_gate = (const float*)d_in[6];
    const float* W_qk   = (const float*)d_in[7];
    const float* b_qk   = (const float*)d_in[8];
    const float* os_g   = (const float*)d_in[9];
    const float* os_b   = (const float*)d_in[10];
    const float* W_out  = (const float*)d_in[11];
    const float* b_out  = (const float*)d_in[12];

    float* out = (float*)d_out;
    float* att = out + (size_t)ROWS * DD;

    f16 *p_nh, *p_nl, *p_vih, *p_vil, *p_wgh, *p_wgl, *p_wqh, *p_wql, *p_woh, *p_wol;
    f16 *p_vr, *p_vT, *p_qh, *p_ql, *p_kh, *p_kl, *p_avgh, *p_avgl, *p_atth;
    float *p_gate;
    cudaGetSymbolAddress((void**)&p_nh, g_nh);
    cudaGetSymbolAddress((void**)&p_nl, g_nl);
    cudaGetSymbolAddress((void**)&p_vih, g_vih);
    cudaGetSymbolAddress((void**)&p_vil, g_vil);
    cudaGetSymbolAddress((void**)&p_wgh, g_wgh);
    cudaGetSymbolAddress((void**)&p_wgl, g_wgl);
    cudaGetSymbolAddress((void**)&p_wqh, g_wqh);
    cudaGetSymbolAddress((void**)&p_wql, g_wql);
    cudaGetSymbolAddress((void**)&p_woh, g_woh);
    cudaGetSymbolAddress((void**)&p_wol, g_wol);
    cudaGetSymbolAddress((void**)&p_gate, g_gate);
    cudaGetSymbolAddress((void**)&p_vr, g_vr);
    cudaGetSymbolAddress((void**)&p_vT, g_vT);
    cudaGetSymbolAddress((void**)&p_qh, g_qh);
    cudaGetSymbolAddress((void**)&p_ql, g_ql);
    cudaGetSymbolAddress((void**)&p_kh, g_kh);
    cudaGetSymbolAddress((void**)&p_kl, g_kl);
    cudaGetSymbolAddress((void**)&p_avgh, g_avgh);
    cudaGetSymbolAddress((void**)&p_avgl, g_avgl);
    cudaGetSymbolAddress((void**)&p_atth, g_atth);

    cudaFuncSetAttribute(sim_mma,  cudaFuncAttributeMaxDynamicSharedMemorySize, SIM_SMEM);
    cudaFuncSetAttribute(attnv_mma, cudaFuncAttributeMaxDynamicSharedMemorySize, AT_SMEM);
    cudaFuncSetAttribute((const void*)hmma_gemm<256,128,MODE_GATE>, cudaFuncAttributeMaxDynamicSharedMemorySize, 2*(32768+2*256*128));
    cudaFuncSetAttribute((const void*)hmma_gemm<256,128,MODE_V>,    cudaFuncAttributeMaxDynamicSharedMemorySize, 2*(32768+2*256*128));
    cudaFuncSetAttribute((const void*)hmma_gemm<128,128,MODE_QK>,   cudaFuncAttributeMaxDynamicSharedMemorySize, 2*(32768+2*128*128));
    cudaFuncSetAttribute((const void*)hmma_gemm<128,256,MODE_OUT>,  cudaFuncAttributeMaxDynamicSharedMemorySize, 2*(32768+2*128*128));

    // prep + splits
    prep_kernel<<<ROWS, 128>>>(query, ln_g, ln_b, p_nh, p_nl);
    split_kernel<<<(ROWS*DD + 255)/256, 256>>>(value, p_vih, p_vil, ROWS*DD);
    wsplit_all<<<320, 256>>>(W_gate, W_qk, W_out, p_wgh, p_wgl, p_wqh, p_wql, p_woh, p_wol);

    // projections (HMMA)
    hmma_gemm<256,128,MODE_GATE><<<128, 512, 2*(32768+2*256*128)>>>(
        p_nh, p_nl, p_wgh, p_wgl, b_gate, nullptr, nullptr,
        p_gate, nullptr, nullptr, nullptr, nullptr, nullptr);
    hmma_gemm<256,128,MODE_V><<<128, 512, 2*(32768+2*256*128)>>>(
        p_vih, p_vil, p_wgh, p_wgl, b_gate, nullptr, nullptr,
        nullptr, p_vr, nullptr, nullptr, nullptr, nullptr);
    hmma_gemm<128,128,MODE_QK><<<128, 512, 2*(32768+2*128*128)>>>(
        p_nh, p_nl, p_wqh, p_wql, b_qk, os_g, os_b,
        nullptr, nullptr, p_qh, p_ql, p_kh, p_kl);
    transpose_f16<<<dim3(HH/32, ROWS/32), dim3(32, 8)>>>(p_vr, p_vT);

    // attention
    sim_mma<<<dim3(SS/256, SS/128, BB), 512, SIM_SMEM>>>(p_qh, p_ql, p_kh, p_kl,
        att, p_atth);
    attnv_mma<<<dim3(SS/128, BB), 512, AT_SMEM>>>(p_atth, p_vT, p_gate,
        p_avgh, p_avgl);

    // output projection (descale by 2^-24 in epilogue)
    hmma_gemm<128,256,MODE_OUT><<<128, 512, 2*(32768+2*128*128)>>>(
        p_avgh, p_avgl, p_woh, p_wol, b_out, nullptr, nullptr,
        out, nullptr, nullptr, nullptr, nullptr, nullptr);
}

// round 10
// speedup vs baseline: 1.3228x; 1.0972x over previous
#include <cuda_runtime.h>
#include <cuda_fp16.h>
#include <math.h>
#include <stdint.h>

#define BB 4
#define SS 4096
#define DD 128
#define HH 256
#define ROWS (BB*SS)   // 16384
#define INV_S2 (1.0f/16777216.0f)   // 2^-24, exact

typedef __half f16;
typedef __half2 f162;

// ---------------- scratch (no allocations allowed) ----------------
__device__ f16 g_nh[ROWS*DD];
__device__ f16 g_nl[ROWS*DD];
__device__ f16 g_vih[ROWS*DD];
__device__ f16 g_vil[ROWS*DD];
__device__ f16 g_wgh[DD*HH];
__device__ f16 g_wgl[DD*HH];
__device__ f16 g_wqh[DD*DD];
__device__ f16 g_wql[DD*DD];
__device__ f16 g_woh[HH*DD];
__device__ f16 g_wol[HH*DD];
__device__ float g_gate[ROWS*HH];
__device__ f16 g_vr[ROWS*HH];                 // v fp16 [seq][256]
__device__ f16 g_vT[HH*ROWS];                 // v^T fp16 [256][16384]
__device__ f16 g_qh[ROWS*DD];
__device__ f16 g_kh[ROWS*DD];
__device__ f16 g_kl[ROWS*DD];
__device__ f16 g_avgh[ROWS*HH];               // scaled by 2^24
__device__ f16 g_avgl[ROWS*HH];
__device__ f16 g_atth[(size_t)ROWS*SS];       // att scaled by 2^24 (fp16)

// ================= PTX helpers (base ISA only) =================
__device__ __forceinline__ uint32_t smem_u32(const void* p) {
    uint32_t a;
    asm("{ .reg .u64 t; cvta.to.shared.u64 t, %1; cvt.u32.u64 %0, t; }" : "=r"(a) : "l"(p));
    return a;
}
__device__ __forceinline__ void cp16(uint32_t s, const void* g) {
    asm volatile("cp.async.cg.shared.global [%0], [%1], 16;" :: "r"(s), "l"(g) : "memory");
}
__device__ __forceinline__ void cp_commit() { asm volatile("cp.async.commit_group;" ::: "memory"); }
template<int N> __device__ __forceinline__ void cp_wait() {
    asm volatile("cp.async.wait_group %0;" :: "n"(N) : "memory");
}
__device__ __forceinline__ void ldm_x4(uint32_t &r0, uint32_t &r1, uint32_t &r2, uint32_t &r3, uint32_t a) {
    asm volatile("ldmatrix.sync.aligned.m8n8.x4.shared.b16 {%0,%1,%2,%3}, [%4];"
        : "=r"(r0), "=r"(r1), "=r"(r2), "=r"(r3) : "r"(a));
}
__device__ __forceinline__ void mma16816(float (&c)[4], const uint32_t (&a)[4], const uint32_t (&b)[2]) {
    asm volatile("mma.sync.aligned.m16n8k16.row.col.f32.f16.f16.f32 "
        "{%0,%1,%2,%3}, {%4,%5,%6,%7}, {%8,%9}, {%0,%1,%2,%3};"
        : "+f"(c[0]), "+f"(c[1]), "+f"(c[2]), "+f"(c[3])
        : "r"(a[0]), "r"(a[1]), "r"(a[2]), "r"(a[3]), "r"(b[0]), "r"(b[1]));
}
// A-frag (m16k16) for one 16-row tile
__device__ __forceinline__ void ldsA(uint32_t (&a)[4], uint32_t base, int mrow, int kt, int lid) {
    int g = lid >> 3, r = lid & 7;
    int row = mrow + ((g & 1) << 3) + r;
    int ch = (kt << 1) + (g >> 1);
    ldm_x4(a[0], a[1], a[2], a[3], base + row * 128 + ((ch ^ (row & 7)) << 4));
}
// TWO adjacent B-frags (k16n8 each, rows nrow..+15) in ONE ldmatrix.x4
__device__ __forceinline__ void ldsB4(uint32_t (&b0)[2], uint32_t (&b1)[2],
                                      uint32_t base, int nrow, int kt, int lid) {
    int g = lid >> 3, r = lid & 7;
    int row = nrow + ((g >> 1) << 3) + r;   // g=0,1 -> first tile rows; g=2,3 -> +8
    int ch = (kt << 1) + (g & 1);
    ldm_x4(b0[0], b0[1], b1[0], b1[1], base + row * 128 + ((ch ^ (row & 7)) << 4));
}
// 512-thread tile loader: [NROWS x 64] f16 k-contiguous -> swizzled smem
template<int NROWS>
__device__ __forceinline__ void load_tile64(uint32_t sbase, const f16* g, size_t rstride, int tid) {
    #pragma unroll
    for (int i = 0; i < NROWS * 8; i += 512) {
        int idx = i + tid;
        int r = idx >> 3, c = idx & 7;
        cp16(sbase + r * 128 + ((c ^ (r & 7)) << 4), g + (size_t)r * rstride + c * 8);
    }
}
__device__ __forceinline__ float silu_f(float x) { return x / (1.0f + expf(-x)); }
__device__ __forceinline__ void split2(float x, f16 &h, f16 &l) {
    h = __float2half_rn(x);
    l = __float2half_rn(x - __half2float(h));
}

// ================= kernel 1: rope + layernorm -> fp16 hi/lo =================
__global__ void prep_kernel(const float* __restrict__ q, const float* __restrict__ g,
                            const float* __restrict__ b,
                            f16* __restrict__ nh, f16* __restrict__ nl) {
    const int row = blockIdx.x;
    const int d = threadIdx.x;
    const int t = row & (SS - 1);
    float x = q[(size_t)row * DD + d];
    float y = x;
    if (d < 32) {
        int j = d >> 1;
        double dinv = pow(10000.0, -(double)j / 16.0);
        float f = (float)t * (float)dinv;
        float c = cosf(f), s = sinf(f);
        float partner = __shfl_xor_sync(0xffffffffu, x, 1);
        y = (d & 1) ? (x * c + partner * s) : (x * c - partner * s);
    }
    __shared__ float red[4];
    float v = y;
    #pragma unroll
    for (int o2 = 16; o2; o2 >>= 1) v += __shfl_xor_sync(0xffffffffu, v, o2);
    if ((threadIdx.x & 31) == 0) red[threadIdx.x >> 5] = v;
    __syncthreads();
    float mu = (red[0] + red[1] + red[2] + red[3]) * (1.0f / 128.0f);
    float dv = y - mu;
    float v2 = dv * dv;
    __syncthreads();
    #pragma unroll
    for (int o2 = 16; o2; o2 >>= 1) v2 += __shfl_xor_sync(0xffffffffu, v2, o2);
    if ((threadIdx.x & 31) == 0) red[threadIdx.x >> 5] = v2;
    __syncthreads();
    float var = (red[0] + red[1] + red[2] + red[3]) * (1.0f / 128.0f);
    float rs = rsqrtf(var + 1e-5f);
    float out = dv * rs * g[d] + b[d];
    f16 h, l; split2(out, h, l);
    nh[(size_t)row * DD + d] = h;
    nl[(size_t)row * DD + d] = l;
}

// ================= elementwise f32 -> fp16 hi/lo split =================
__global__ void split_kernel(const float* __restrict__ x, f16* __restrict__ xh,
                             f16* __restrict__ xl, int n) {
    int i = blockIdx.x * 256 + threadIdx.x;
    if (i < n) {
        f16 h, l; split2(x[i], h, l);
        xh[i] = h; xl[i] = l;
    }
}

// ================= all weights transpose+split in ONE launch =================
__global__ void wsplit_all(const float* __restrict__ Wg, const float* __restrict__ Wq,
                           const float* __restrict__ Wo,
                           f16* __restrict__ wgh, f16* __restrict__ wgl,
                           f16* __restrict__ wqh, f16* __restrict__ wql,
                           f16* __restrict__ woh, f16* __restrict__ wol) {
    int i = blockIdx.x * 256 + threadIdx.x;
    const float* W; f16 *wh, *wl; int K, N, off;
    if (i < 32768)       { W = Wg; wh = wgh; wl = wgl; K = 128; N = 256; off = i; }
    else if (i < 49152)  { W = Wq; wh = wqh; wl = wql; K = 128; N = 128; off = i - 32768; }
    else if (i < 81920)  { W = Wo; wh = woh; wl = wol; K = 256; N = 128; off = i - 49152; }
    else return;
    int k = off / N, n = off % N;
    f16 h, l; split2(W[(size_t)k * N + n], h, l);
    wh[(size_t)n * K + k] = h;
    wl[(size_t)n * K + k] = l;
}

// ================= fp16 transpose: [16384][256] -> [256][16384] ============
__global__ void transpose_f16(const f16* __restrict__ v, f16* __restrict__ vt) {
    __shared__ f16 tile[32][33];
    int x = blockIdx.x * 32 + threadIdx.x;
    int y = blockIdx.y * 32 + threadIdx.y;
    #pragma unroll
    for (int dy = 0; dy < 32; dy += 8)
        tile[threadIdx.y + dy][threadIdx.x] = v[(size_t)(y + dy) * HH + x];
    __syncthreads();
    int xo = blockIdx.y * 32 + threadIdx.x;
    int yo = blockIdx.x * 32 + threadIdx.y;
    #pragma unroll
    for (int dy = 0; dy < 32; dy += 8)
        vt[(size_t)(yo + dy) * ROWS + xo] = tile[threadIdx.x][threadIdx.y + dy];
}

// ================= generic HMMA projection GEMM (512 thr, 16 warps) ========
#define MODE_GATE 0
#define MODE_V    1
#define MODE_QK   2
#define MODE_OUT  3   // acc is scaled by 2^24; multiply by INV_S2 before bias

template<int NDIM, int KDIM, int MODE>
__global__ __launch_bounds__(512) void hmma_gemm(
    const f16* __restrict__ Ah_g, const f16* __restrict__ Al_g,
    const f16* __restrict__ Bh_g, const f16* __restrict__ Bl_g,
    const float* __restrict__ bias, const float* __restrict__ gam,
    const float* __restrict__ bet,
    float* __restrict__ O0f, f16* __restrict__ O0h,
    f16* __restrict__ qh, f16* __restrict__ kh, f16* __restrict__ kl)
{
    constexpr int NSLAB = KDIM / 64;
    constexpr int BSTG = NDIM * 128;
    constexpr int STG = 32768 + 2 * BSTG;
    constexpr int NT = NDIM / 32;
    extern __shared__ __align__(128) char smem[];
    const uint32_t sb = smem_u32(smem);
    const int tid = threadIdx.x, wid = tid >> 5, lid = tid & 31;
    const int m0 = blockIdx.x * 128;
    const f16* Ahp = Ah_g + (size_t)m0 * KDIM;
    const f16* Alp = Al_g + (size_t)m0 * KDIM;

    const int wm = (wid >> 2) * 32;
    const int wn = (wid & 3) * (NDIM / 4);
    float acc[2][NT][4];
    #pragma unroll
    for (int i = 0; i < 2; i++)
        #pragma unroll
        for (int j = 0; j < NT; j++)
            #pragma unroll
            for (int e = 0; e < 4; e++) acc[i][j][e] = 0.f;

    auto load_slab = [&](int s, uint32_t base) {
        load_tile64<128>(base,          Ahp + s * 64, KDIM, tid);
        load_tile64<128>(base + 16384,  Alp + s * 64, KDIM, tid);
        load_tile64<NDIM>(base + 32768, Bh_g + s * 64, KDIM, tid);
        load_tile64<NDIM>(base + 32768 + BSTG, Bl_g + s * 64, KDIM, tid);
        cp_commit();
    };
    auto compute = [&](uint32_t base) {
        const uint32_t Ah = base, Al = base + 16384;
        const uint32_t Bh = base + 32768, Bl = base + 32768 + BSTG;
        #pragma unroll
        for (int kt = 0; kt < 4; kt++) {
            uint32_t ah[2][4], al[2][4], bh[NT][2], bl[NT][2];
            #pragma unroll
            for (int mt = 0; mt < 2; mt++) ldsA(ah[mt], Ah, wm + mt*16, kt, lid);
            #pragma unroll
            for (int nt = 0; nt < NT; nt += 2) ldsB4(bh[nt], bh[nt+1], Bh, wn + nt*8, kt, lid);
            #pragma unroll
            for (int mt = 0; mt < 2; mt++)
                #pragma unroll
                for (int nt = 0; nt < NT; nt++) mma16816(acc[mt][nt], ah[mt], bh[nt]);
            #pragma unroll
            for (int mt = 0; mt < 2; mt++) ldsA(al[mt], Al, wm + mt*16, kt, lid);
            #pragma unroll
            for (int mt = 0; mt < 2; mt++)
                #pragma unroll
                for (int nt = 0; nt < NT; nt++) mma16816(acc[mt][nt], al[mt], bh[nt]);
            #pragma unroll
            for (int nt = 0; nt < NT; nt += 2) ldsB4(bl[nt], bl[nt+1], Bl, wn + nt*8, kt, lid);
            #pragma unroll
            for (int mt = 0; mt < 2; mt++)
                #pragma unroll
                for (int nt = 0; nt < NT; nt++) mma16816(acc[mt][nt], ah[mt], bl[nt]);
        }
    };

    load_slab(0, sb);
    if (NSLAB > 1) load_slab(1, sb + STG);
    #pragma unroll
    for (int j = 0; j < NSLAB; j++) {
        if (j + 1 < NSLAB) cp_wait<1>(); else cp_wait<0>();
        __syncthreads();
        compute(sb + (j & 1) * STG);
        if (j + 2 < NSLAB) { __syncthreads(); load_slab(j + 2, sb + (j & 1) * STG); }
    }

    const float scl = (MODE == MODE_OUT) ? INV_S2 : 1.0f;
    const int lr = lid >> 2, lc = (lid & 3) * 2;
    #pragma unroll
    for (int mt = 0; mt < 2; mt++) {
        #pragma unroll
        for (int h2 = 0; h2 < 2; h2++) {
            const int row = m0 + wm + mt * 16 + h2 * 8 + lr;
            #pragma unroll
            for (int nt = 0; nt < NT; nt++) {
                const int col = wn + nt * 8 + lc;
                float x0 = acc[mt][nt][h2*2+0] * scl + bias[col];
                float x1 = acc[mt][nt][h2*2+1] * scl + bias[col+1];
                if (MODE == MODE_GATE) {
                    *(float2*)(O0f + (size_t)row * NDIM + col) = make_float2(silu_f(x0), silu_f(x1));
                } else if (MODE == MODE_V) {
                    f162 p;
                    p.x = __float2half_rn(silu_f(x0)); p.y = __float2half_rn(silu_f(x1));
                    *(f162*)(O0h + (size_t)row * NDIM + col) = p;
                } else if (MODE == MODE_QK) {
                    float y0 = silu_f(x0), y1 = silu_f(x1);
                    float q0 = y0 * gam[col] + bet[col], q1 = y1 * gam[col+1] + bet[col+1];
                    float k0 = y0 * gam[NDIM+col] + bet[NDIM+col], k1 = y1 * gam[NDIM+col+1] + bet[NDIM+col+1];
                    f162 hp, lp;
                    hp.x = __float2half_rn(q0); hp.y = __float2half_rn(q1);
                    *(f162*)(qh + (size_t)row * NDIM + col) = hp;   // q: hi only (2-pass sim)
                    split2(k0, hp.x, lp.x); split2(k1, hp.y, lp.y);
                    *(f162*)(kh + (size_t)row * NDIM + col) = hp;
                    *(f162*)(kl + (size_t)row * NDIM + col) = lp;
                } else {
                    *(float2*)(O0f + (size_t)row * NDIM + col) = make_float2(x0, x1);
                }
            }
        }
    }
}

// ================= big GEMM 1: att = relu(q@k^T/S)^2 (fp16 2-pass) =========
// q_hi x (k_hi + k_lo). atth stores relu(q@k^T)^2 (att * 2^24); f32 att * 2^-24.
#define SIM_STG 81920   // Ah 16K | Bh 32K | Bl 32K
#define SIM_SMEM (2*SIM_STG)

__global__ __launch_bounds__(512) void sim_mma(
    const f16* __restrict__ qh_g,
    const f16* __restrict__ kh_g, const f16* __restrict__ kl_g,
    float* __restrict__ att, f16* __restrict__ atth)
{
    extern __shared__ __align__(128) char smem[];
    const uint32_t sb = smem_u32(smem);
    const int tid = threadIdx.x, wid = tid >> 5, lid = tid & 31;
    const int b = blockIdx.z, m0 = blockIdx.y * 128, n0 = blockIdx.x * 256;
    const f16* qhp = qh_g + ((size_t)b * SS + m0) * DD;
    const f16* khp = kh_g + ((size_t)b * SS + n0) * DD;
    const f16* klp = kl_g + ((size_t)b * SS + n0) * DD;

    const int wm = (wid >> 2) * 32, wn = (wid & 3) * 64;
    float acc[2][8][4];
    #pragma unroll
    for (int i = 0; i < 2; i++)
        #pragma unroll
        for (int j = 0; j < 8; j++)
            #pragma unroll
            for (int e = 0; e < 4; e++) acc[i][j][e] = 0.f;

    auto load_half = [&](int h, uint32_t base) {
        load_tile64<128>(base,         qhp + h * 64, DD, tid);
        load_tile64<256>(base + 16384, khp + h * 64, DD, tid);
        load_tile64<256>(base + 49152, klp + h * 64, DD, tid);
        cp_commit();
    };
    auto compute = [&](uint32_t base) {
        const uint32_t Ah = base, Bh = base + 16384, Bl = base + 49152;
        #pragma unroll
        for (int kt = 0; kt < 4; kt++) {
            uint32_t ah[2][4], bh[8][2], bl[8][2];
            #pragma unroll
            for (int mt = 0; mt < 2; mt++) ldsA(ah[mt], Ah, wm + mt*16, kt, lid);
            #pragma unroll
            for (int nt = 0; nt < 8; nt += 2) ldsB4(bh[nt], bh[nt+1], Bh, wn + nt*8, kt, lid);
            #pragma unroll
            for (int mt = 0; mt < 2; mt++)
                #pragma unroll
                for (int nt = 0; nt < 8; nt++) mma16816(acc[mt][nt], ah[mt], bh[nt]);
            #pragma unroll
            for (int nt = 0; nt < 8; nt += 2) ldsB4(bl[nt], bl[nt+1], Bl, wn + nt*8, kt, lid);
            #pragma unroll
            for (int mt = 0; mt < 2; mt++)
                #pragma unroll
                for (int nt = 0; nt < 8; nt++) mma16816(acc[mt][nt], ah[mt], bl[nt]);
        }
    };

    load_half(0, sb);
    load_half(1, sb + SIM_STG);
    cp_wait<1>(); __syncthreads();
    compute(sb);
    cp_wait<0>(); __syncthreads();
    compute(sb + SIM_STG);

    const int lr = lid >> 2, lc = (lid & 3) * 2;
    float* attb = att + (size_t)b * SS * SS;
    f16* hib = atth + (size_t)b * SS * SS;
    #pragma unroll
    for (int mt = 0; mt < 2; mt++) {
        #pragma unroll
        for (int h2 = 0; h2 < 2; h2++) {
            int row = m0 + wm + mt * 16 + h2 * 8 + lr;
            size_t ro = (size_t)row * SS;
            #pragma unroll
            for (int nt = 0; nt < 8; nt++) {
                int col = n0 + wn + nt * 8 + lc;
                float p0 = fmaxf(acc[mt][nt][h2*2+0], 0.f);
                float p1 = fmaxf(acc[mt][nt][h2*2+1], 0.f);
                float sa0 = p0 * p0, sa1 = p1 * p1;        // att * 2^24
                *(float2*)(attb + ro + col) = make_float2(sa0 * INV_S2, sa1 * INV_S2);
                f162 hp;
                hp.x = __float2half_rn(sa0); hp.y = __float2half_rn(sa1);
                *(f162*)(hib + ro + col) = hp;
            }
        }
    }
}

// ================= big GEMM 2: av = atth @ vT (fp16 1-pass), *gate =========
#define AT_STG 49152    // A 16K | v 32K
#define AT_SMEM (3*AT_STG)
#define AT_NS 64

__global__ __launch_bounds__(512) void attnv_mma(
    const f16* __restrict__ atth, const f16* __restrict__ vt,
    const float* __restrict__ gate,
    f16* __restrict__ avgh, f16* __restrict__ avgl)
{
    extern __shared__ __align__(128) char smem[];
    const uint32_t sb = smem_u32(smem);
    const int tid = threadIdx.x, wid = tid >> 5, lid = tid & 31;
    const int b = blockIdx.y, m0 = blockIdx.x * 128;
    const f16* ahp = atth + (size_t)b * SS * SS + (size_t)m0 * SS;
    const f16* vp  = vt + (size_t)b * SS;

    const int wm = (wid >> 2) * 32, wn = (wid & 3) * 64;
    float acc[2][8][4];
    #pragma unroll
    for (int i = 0; i < 2; i++)
        #pragma unroll
        for (int j = 0; j < 8; j++)
            #pragma unroll
            for (int e = 0; e < 4; e++) acc[i][j][e] = 0.f;

    auto load_slab = [&](int j, int s) {
        uint32_t base = sb + s * AT_STG;
        load_tile64<128>(base,         ahp + j * 64, SS, tid);
        load_tile64<256>(base + 16384, vp + j * 64, ROWS, tid);
        cp_commit();
    };
    auto compute = [&](int s) {
        uint32_t base = sb + s * AT_STG;
        const uint32_t Aa = base, Bv = base + 16384;
        #pragma unroll
        for (int kt = 0; kt < 4; kt++) {
            uint32_t af[2][4], bf[8][2];
            #pragma unroll
            for (int mt = 0; mt < 2; mt++) ldsA(af[mt], Aa, wm + mt*16, kt, lid);
            #pragma unroll
            for (int nt = 0; nt < 8; nt += 2) ldsB4(bf[nt], bf[nt+1], Bv, wn + nt*8, kt, lid);
            #pragma unroll
            for (int mt = 0; mt < 2; mt++)
                #pragma unroll
                for (int nt = 0; nt < 8; nt++) mma16816(acc[mt][nt], af[mt], bf[nt]);
        }
    };

    load_slab(0, 0);
    load_slab(1, 1);
    for (int j = 0; j < AT_NS; j++) {
        if (j + 1 < AT_NS) cp_wait<1>(); else cp_wait<0>();
        __syncthreads();
        if (j + 2 < AT_NS) load_slab(j + 2, (j + 2) % 3);
        compute(j % 3);
    }

    const int lr = lid >> 2, lc = (lid & 3) * 2;
    #pragma unroll
    for (int mt = 0; mt < 2; mt++) {
        #pragma unroll
        for (int h2 = 0; h2 < 2; h2++) {
            size_t grow = (size_t)b * SS + m0 + wm + mt * 16 + h2 * 8 + lr;
            const float* gp = gate + grow * HH;
            f16* hp_ = avgh + grow * HH;
            f16* lp_ = avgl + grow * HH;
            #pragma unroll
            for (int nt = 0; nt < 8; nt++) {
                int col = wn + nt * 8 + lc;
                float2 g2 = *(const float2*)(gp + col);
                float o0 = acc[mt][nt][h2*2+0] * g2.x;   // scaled by 2^24
                float o1 = acc[mt][nt][h2*2+1] * g2.y;
                f162 hh, ll;
                split2(o0, hh.x, ll.x); split2(o1, hh.y, ll.y);
                *(f162*)(hp_ + col) = hh;
                *(f162*)(lp_ + col) = ll;
            }
        }
    }
}

// ================= launch =================
extern "C" void kernel_launch(void* const* d_in, const int* in_sizes, int n_in,
                              void* d_out, int out_size)
{
    const float* query  = (const float*)d_in[0];
    const float* value  = (const float*)d_in[2];
    const float* ln_g   = (const float*)d_in[3];
    const float* ln_b   = (const float*)d_in[4];
    const float* W_gate = (const float*)d_in[5];
    const float* b_gate = (const float*)d_in[6];
    const float* W_qk   = (const float*)d_in[7];
    const float* b_qk   = (const float*)d_in[8];
    const float* os_g   = (const float*)d_in[9];
    const float* os_b   = (const float*)d_in[10];
    const float* W_out  = (const float*)d_in[11];
    const float* b_out  = (const float*)d_in[12];

    float* out = (float*)d_out;
    float* att = out + (size_t)ROWS * DD;

    f16 *p_nh, *p_nl, *p_vih, *p_vil, *p_wgh, *p_wgl, *p_wqh, *p_wql, *p_woh, *p_wol;
    f16 *p_vr, *p_vT, *p_qh, *p_kh, *p_kl, *p_avgh, *p_avgl, *p_atth;
    float *p_gate;
    cudaGetSymbolAddress((void**)&p_nh, g_nh);
    cudaGetSymbolAddress((void**)&p_nl, g_nl);
    cudaGetSymbolAddress((void**)&p_vih, g_vih);
    cudaGetSymbolAddress((void**)&p_vil, g_vil);
    cudaGetSymbolAddress((void**)&p_wgh, g_wgh);
    cudaGetSymbolAddress((void**)&p_wgl, g_wgl);
    cudaGetSymbolAddress((void**)&p_wqh, g_wqh);
    cudaGetSymbolAddress((void**)&p_wql, g_wql);
    cudaGetSymbolAddress((void**)&p_woh, g_woh);
    cudaGetSymbolAddress((void**)&p_wol, g_wol);
    cudaGetSymbolAddress((void**)&p_gate, g_gate);
    cudaGetSymbolAddress((void**)&p_vr, g_vr);
    cudaGetSymbolAddress((void**)&p_vT, g_vT);
    cudaGetSymbolAddress((void**)&p_qh, g_qh);
    cudaGetSymbolAddress((void**)&p_kh, g_kh);
    cudaGetSymbolAddress((void**)&p_kl, g_kl);
    cudaGetSymbolAddress((void**)&p_avgh, g_avgh);
    cudaGetSymbolAddress((void**)&p_avgl, g_avgl);
    cudaGetSymbolAddress((void**)&p_atth, g_atth);

    cudaFuncSetAttribute(sim_mma,  cudaFuncAttributeMaxDynamicSharedMemorySize, SIM_SMEM);
    cudaFuncSetAttribute(attnv_mma, cudaFuncAttributeMaxDynamicSharedMemorySize, AT_SMEM);
    cudaFuncSetAttribute((const void*)hmma_gemm<256,128,MODE_GATE>, cudaFuncAttributeMaxDynamicSharedMemorySize, 2*(32768+2*256*128));
    cudaFuncSetAttribute((const void*)hmma_gemm<256,128,MODE_V>,    cudaFuncAttributeMaxDynamicSharedMemorySize, 2*(32768+2*256*128));
    cudaFuncSetAttribute((const void*)hmma_gemm<128,128,MODE_QK>,   cudaFuncAttributeMaxDynamicSharedMemorySize, 2*(32768+2*128*128));
    cudaFuncSetAttribute((const void*)hmma_gemm<128,256,MODE_OUT>,  cudaFuncAttributeMaxDynamicSharedMemorySize, 2*(32768+2*128*128));

    // prep + splits
    prep_kernel<<<ROWS, 128>>>(query, ln_g, ln_b, p_nh, p_nl);
    split_kernel<<<(ROWS*DD + 255)/256, 256>>>(value, p_vih, p_vil, ROWS*DD);
    wsplit_all<<<320, 256>>>(W_gate, W_qk, W_out, p_wgh, p_wgl, p_wqh, p_wql, p_woh, p_wol);

    // projections (HMMA)
    hmma_gemm<256,128,MODE_GATE><<<128, 512, 2*(32768+2*256*128)>>>(
        p_nh, p_nl, p_wgh, p_wgl, b_gate, nullptr, nullptr,
        p_gate, nullptr, nullptr, nullptr, nullptr);
    hmma_gemm<256,128,MODE_V><<<128, 512, 2*(32768+2*256*128)>>>(
        p_vih, p_vil, p_wgh, p_wgl, b_gate, nullptr, nullptr,
        nullptr, p_vr, nullptr, nullptr, nullptr);
    hmma_gemm<128,128,MODE_QK><<<128, 512, 2*(32768+2*128*128)>>>(
        p_nh, p_nl, p_wqh, p_wql, b_qk, os_g, os_b,
        nullptr, nullptr, p_qh, p_kh, p_kl);
    transpose_f16<<<dim3(HH/32, ROWS/32), dim3(32, 8)>>>(p_vr, p_vT);

    // attention
    sim_mma<<<dim3(SS/256, SS/128, BB), 512, SIM_SMEM>>>(p_qh, p_kh, p_kl,
        att, p_atth);
    attnv_mma<<<dim3(SS/128, BB), 512, AT_SMEM>>>(p_atth, p_vT, p_gate,
        p_avgh, p_avgl);

    // output projection (descale by 2^-24 in epilogue)
    hmma_gemm<128,256,MODE_OUT><<<128, 512, 2*(32768+2*128*128)>>>(
        p_avgh, p_avgl, p_woh, p_wol, b_out, nullptr, nullptr,
        out, nullptr, nullptr, nullptr, nullptr);
}

// round 12
// speedup vs baseline: 1.3367x; 1.0105x over previous
#include <cuda_runtime.h>
#include <cuda_fp16.h>
#include <math.h>
#include <stdint.h>

#define BB 4
#define SS 4096
#define DD 128
#define HH 256
#define ROWS (BB*SS)   // 16384
#define INV_S2 (1.0f/16777216.0f)   // 2^-24, exact

typedef __half f16;
typedef __half2 f162;

// ---------------- scratch (no allocations allowed) ----------------
__device__ f16 g_nh[ROWS*DD];
__device__ f16 g_vih[ROWS*DD];
__device__ f16 g_wgh[DD*HH];
__device__ f16 g_wgl[DD*HH];
__device__ f16 g_wqh[DD*DD];
__device__ f16 g_wql[DD*DD];
__device__ f16 g_woh[HH*DD];
__device__ f16 g_wol[HH*DD];
__device__ float g_gate[ROWS*HH];
__device__ f16 g_vr[ROWS*HH];                 // v fp16 [seq][256]
__device__ f16 g_vT[HH*ROWS];                 // v^T fp16 [256][16384]
__device__ f16 g_qh[ROWS*DD];
__device__ f16 g_kh[ROWS*DD];
__device__ f16 g_kl[ROWS*DD];
__device__ f16 g_avgh[ROWS*HH];               // (att@v)*gate, scaled 2^24, hi only
__device__ f16 g_atth[(size_t)ROWS*SS];       // att scaled by 2^24 (fp16)

// ================= PTX helpers (base ISA only) =================
__device__ __forceinline__ uint32_t smem_u32(const void* p) {
    uint32_t a;
    asm("{ .reg .u64 t; cvta.to.shared.u64 t, %1; cvt.u32.u64 %0, t; }" : "=r"(a) : "l"(p));
    return a;
}
__device__ __forceinline__ void cp16(uint32_t s, const void* g) {
    asm volatile("cp.async.cg.shared.global [%0], [%1], 16;" :: "r"(s), "l"(g) : "memory");
}
__device__ __forceinline__ void cp_commit() { asm volatile("cp.async.commit_group;" ::: "memory"); }
template<int N> __device__ __forceinline__ void cp_wait() {
    asm volatile("cp.async.wait_group %0;" :: "n"(N) : "memory");
}
__device__ __forceinline__ void ldm_x4(uint32_t &r0, uint32_t &r1, uint32_t &r2, uint32_t &r3, uint32_t a) {
    asm volatile("ldmatrix.sync.aligned.m8n8.x4.shared.b16 {%0,%1,%2,%3}, [%4];"
        : "=r"(r0), "=r"(r1), "=r"(r2), "=r"(r3) : "r"(a));
}
__device__ __forceinline__ void mma16816(float (&c)[4], const uint32_t (&a)[4], const uint32_t (&b)[2]) {
    asm volatile("mma.sync.aligned.m16n8k16.row.col.f32.f16.f16.f32 "
        "{%0,%1,%2,%3}, {%4,%5,%6,%7}, {%8,%9}, {%0,%1,%2,%3};"
        : "+f"(c[0]), "+f"(c[1]), "+f"(c[2]), "+f"(c[3])
        : "r"(a[0]), "r"(a[1]), "r"(a[2]), "r"(a[3]), "r"(b[0]), "r"(b[1]));
}
// A-frag (m16k16) for one 16-row tile
__device__ __forceinline__ void ldsA(uint32_t (&a)[4], uint32_t base, int mrow, int kt, int lid) {
    int g = lid >> 3, r = lid & 7;
    int row = mrow + ((g & 1) << 3) + r;
    int ch = (kt << 1) + (g >> 1);
    ldm_x4(a[0], a[1], a[2], a[3], base + row * 128 + ((ch ^ (row & 7)) << 4));
}
// TWO adjacent B-frags (k16n8 each) in ONE ldmatrix.x4
__device__ __forceinline__ void ldsB4(uint32_t (&b0)[2], uint32_t (&b1)[2],
                                      uint32_t base, int nrow, int kt, int lid) {
    int g = lid >> 3, r = lid & 7;
    int row = nrow + ((g >> 1) << 3) + r;
    int ch = (kt << 1) + (g & 1);
    ldm_x4(b0[0], b0[1], b1[0], b1[1], base + row * 128 + ((ch ^ (row & 7)) << 4));
}
// 512-thread tile loader: [NROWS x 64] f16 k-contiguous -> swizzled smem
template<int NROWS>
__device__ __forceinline__ void load_tile64(uint32_t sbase, const f16* g, size_t rstride, int tid) {
    #pragma unroll
    for (int i = 0; i < NROWS * 8; i += 512) {
        int idx = i + tid;
        int r = idx >> 3, c = idx & 7;
        cp16(sbase + r * 128 + ((c ^ (r & 7)) << 4), g + (size_t)r * rstride + c * 8);
    }
}
__device__ __forceinline__ float silu_f(float x) { return x / (1.0f + expf(-x)); }
__device__ __forceinline__ void split2(float x, f16 &h, f16 &l) {
    h = __float2half_rn(x);
    l = __float2half_rn(x - __half2float(h));
}

// ================= kernel 1: rope + layernorm -> fp16 hi =================
__global__ void prep_kernel(const float* __restrict__ q, const float* __restrict__ g,
                            const float* __restrict__ b, f16* __restrict__ nh) {
    const int row = blockIdx.x;
    const int d = threadIdx.x;
    const int t = row & (SS - 1);
    float x = q[(size_t)row * DD + d];
    float y = x;
    if (d < 32) {
        int j = d >> 1;
        double dinv = pow(10000.0, -(double)j / 16.0);
        float f = (float)t * (float)dinv;
        float c = cosf(f), s = sinf(f);
        float partner = __shfl_xor_sync(0xffffffffu, x, 1);
        y = (d & 1) ? (x * c + partner * s) : (x * c - partner * s);
    }
    __shared__ float red[4];
    float v = y;
    #pragma unroll
    for (int o2 = 16; o2; o2 >>= 1) v += __shfl_xor_sync(0xffffffffu, v, o2);
    if ((threadIdx.x & 31) == 0) red[threadIdx.x >> 5] = v;
    __syncthreads();
    float mu = (red[0] + red[1] + red[2] + red[3]) * (1.0f / 128.0f);
    float dv = y - mu;
    float v2 = dv * dv;
    __syncthreads();
    #pragma unroll
    for (int o2 = 16; o2; o2 >>= 1) v2 += __shfl_xor_sync(0xffffffffu, v2, o2);
    if ((threadIdx.x & 31) == 0) red[threadIdx.x >> 5] = v2;
    __syncthreads();
    float var = (red[0] + red[1] + red[2] + red[3]) * (1.0f / 128.0f);
    float rs = rsqrtf(var + 1e-5f);
    float out = dv * rs * g[d] + b[d];
    nh[(size_t)row * DD + d] = __float2half_rn(out);
}

// ================= elementwise f32 -> fp16 convert =================
__global__ void cvt_kernel(const float* __restrict__ x, f16* __restrict__ xh, int n) {
    int i = blockIdx.x * 256 + threadIdx.x;
    if (i < n) xh[i] = __float2half_rn(x[i]);
}

// ================= all weights transpose+split in ONE launch =================
__global__ void wsplit_all(const float* __restrict__ Wg, const float* __restrict__ Wq,
                           const float* __restrict__ Wo,
                           f16* __restrict__ wgh, f16* __restrict__ wgl,
                           f16* __restrict__ wqh, f16* __restrict__ wql,
                           f16* __restrict__ woh, f16* __restrict__ wol) {
    int i = blockIdx.x * 256 + threadIdx.x;
    const float* W; f16 *wh, *wl; int K, N, off;
    if (i < 32768)       { W = Wg; wh = wgh; wl = wgl; K = 128; N = 256; off = i; }
    else if (i < 49152)  { W = Wq; wh = wqh; wl = wql; K = 128; N = 128; off = i - 32768; }
    else if (i < 81920)  { W = Wo; wh = woh; wl = wol; K = 256; N = 128; off = i - 49152; }
    else return;
    int k = off / N, n = off % N;
    f16 h, l; split2(W[(size_t)k * N + n], h, l);
    wh[(size_t)n * K + k] = h;
    wl[(size_t)n * K + k] = l;
}

// ================= fp16 transpose: [16384][256] -> [256][16384] ============
__global__ void transpose_f16(const f16* __restrict__ v, f16* __restrict__ vt) {
    __shared__ f16 tile[32][33];
    int x = blockIdx.x * 32 + threadIdx.x;
    int y = blockIdx.y * 32 + threadIdx.y;
    #pragma unroll
    for (int dy = 0; dy < 32; dy += 8)
        tile[threadIdx.y + dy][threadIdx.x] = v[(size_t)(y + dy) * HH + x];
    __syncthreads();
    int xo = blockIdx.y * 32 + threadIdx.x;
    int yo = blockIdx.x * 32 + threadIdx.y;
    #pragma unroll
    for (int dy = 0; dy < 32; dy += 8)
        vt[(size_t)(yo + dy) * ROWS + xo] = tile[threadIdx.x][threadIdx.y + dy];
}

// ====== generic HMMA projection GEMM, 2-pass: A_hi x (B_hi + B_lo) =========
#define MODE_GATE 0
#define MODE_V    1
#define MODE_QK   2
#define MODE_OUT  3   // acc scaled by 2^24; multiply by INV_S2 before bias

template<int NDIM, int KDIM, int MODE>
__global__ __launch_bounds__(512) void hmma_gemm(
    const f16* __restrict__ Ah_g,
    const f16* __restrict__ Bh_g, const f16* __restrict__ Bl_g,
    const float* __restrict__ bias, const float* __restrict__ gam,
    const float* __restrict__ bet,
    float* __restrict__ O0f, f16* __restrict__ O0h,
    f16* __restrict__ qh, f16* __restrict__ kh, f16* __restrict__ kl)
{
    constexpr int NSLAB = KDIM / 64;
    constexpr int BSTG = NDIM * 128;
    constexpr int STG = 16384 + 2 * BSTG;
    constexpr int NT = NDIM / 32;
    extern __shared__ __align__(128) char smem[];
    const uint32_t sb = smem_u32(smem);
    const int tid = threadIdx.x, wid = tid >> 5, lid = tid & 31;
    const int m0 = blockIdx.x * 128;
    const f16* Ahp = Ah_g + (size_t)m0 * KDIM;

    const int wm = (wid >> 2) * 32;
    const int wn = (wid & 3) * (NDIM / 4);
    float acc[2][NT][4];
    #pragma unroll
    for (int i = 0; i < 2; i++)
        #pragma unroll
        for (int j = 0; j < NT; j++)
            #pragma unroll
            for (int e = 0; e < 4; e++) acc[i][j][e] = 0.f;

    auto load_slab = [&](int s, uint32_t base) {
        load_tile64<128>(base,          Ahp + s * 64, KDIM, tid);
        load_tile64<NDIM>(base + 16384, Bh_g + s * 64, KDIM, tid);
        load_tile64<NDIM>(base + 16384 + BSTG, Bl_g + s * 64, KDIM, tid);
        cp_commit();
    };
    auto compute = [&](uint32_t base) {
        const uint32_t Ah = base;
        const uint32_t Bh = base + 16384, Bl = base + 16384 + BSTG;
        #pragma unroll
        for (int kt = 0; kt < 4; kt++) {
            uint32_t ah[2][4], bh[NT][2], bl[NT][2];
            #pragma unroll
            for (int mt = 0; mt < 2; mt++) ldsA(ah[mt], Ah, wm + mt*16, kt, lid);
            #pragma unroll
            for (int nt = 0; nt < NT; nt += 2) ldsB4(bh[nt], bh[nt+1], Bh, wn + nt*8, kt, lid);
            #pragma unroll
            for (int mt = 0; mt < 2; mt++)
                #pragma unroll
                for (int nt = 0; nt < NT; nt++) mma16816(acc[mt][nt], ah[mt], bh[nt]);
            #pragma unroll
            for (int nt = 0; nt < NT; nt += 2) ldsB4(bl[nt], bl[nt+1], Bl, wn + nt*8, kt, lid);
            #pragma unroll
            for (int mt = 0; mt < 2; mt++)
                #pragma unroll
                for (int nt = 0; nt < NT; nt++) mma16816(acc[mt][nt], ah[mt], bl[nt]);
        }
    };

    load_slab(0, sb);
    if (NSLAB > 1) load_slab(1, sb + STG);
    #pragma unroll
    for (int j = 0; j < NSLAB; j++) {
        if (j + 1 < NSLAB) cp_wait<1>(); else cp_wait<0>();
        __syncthreads();
        compute(sb + (j & 1) * STG);
        if (j + 2 < NSLAB) { __syncthreads(); load_slab(j + 2, sb + (j & 1) * STG); }
    }

    const float scl = (MODE == MODE_OUT) ? INV_S2 : 1.0f;
    const int lr = lid >> 2, lc = (lid & 3) * 2;
    #pragma unroll
    for (int mt = 0; mt < 2; mt++) {
        #pragma unroll
        for (int h2 = 0; h2 < 2; h2++) {
            const int row = m0 + wm + mt * 16 + h2 * 8 + lr;
            #pragma unroll
            for (int nt = 0; nt < NT; nt++) {
                const int col = wn + nt * 8 + lc;
                float x0 = acc[mt][nt][h2*2+0] * scl + bias[col];
                float x1 = acc[mt][nt][h2*2+1] * scl + bias[col+1];
                if (MODE == MODE_GATE) {
                    *(float2*)(O0f + (size_t)row * NDIM + col) = make_float2(silu_f(x0), silu_f(x1));
                } else if (MODE == MODE_V) {
                    f162 p;
                    p.x = __float2half_rn(silu_f(x0)); p.y = __float2half_rn(silu_f(x1));
                    *(f162*)(O0h + (size_t)row * NDIM + col) = p;
                } else if (MODE == MODE_QK) {
                    float y0 = silu_f(x0), y1 = silu_f(x1);
                    float q0 = y0 * gam[col] + bet[col], q1 = y1 * gam[col+1] + bet[col+1];
                    float k0 = y0 * gam[NDIM+col] + bet[NDIM+col], k1 = y1 * gam[NDIM+col+1] + bet[NDIM+col+1];
                    f162 hp, lp;
                    hp.x = __float2half_rn(q0); hp.y = __float2half_rn(q1);
                    *(f162*)(qh + (size_t)row * NDIM + col) = hp;   // q: hi only
                    split2(k0, hp.x, lp.x); split2(k1, hp.y, lp.y);
                    *(f162*)(kh + (size_t)row * NDIM + col) = hp;
                    *(f162*)(kl + (size_t)row * NDIM + col) = lp;
                } else {
                    *(float2*)(O0f + (size_t)row * NDIM + col) = make_float2(x0, x1);
                }
            }
        }
    }
}

// ================= big GEMM 1: att = relu(q@k^T/S)^2 (fp16 2-pass) =========
#define SIM_STG 81920   // Ah 16K | Bh 32K | Bl 32K
#define SIM_SMEM (2*SIM_STG)

__global__ __launch_bounds__(512) void sim_mma(
    const f16* __restrict__ qh_g,
    const f16* __restrict__ kh_g, const f16* __restrict__ kl_g,
    float* __restrict__ att, f16* __restrict__ atth)
{
    extern __shared__ __align__(128) char smem[];
    const uint32_t sb = smem_u32(smem);
    const int tid = threadIdx.x, wid = tid >> 5, lid = tid & 31;
    const int b = blockIdx.z, m0 = blockIdx.y * 128, n0 = blockIdx.x * 256;
    const f16* qhp = qh_g + ((size_t)b * SS + m0) * DD;
    const f16* khp = kh_g + ((size_t)b * SS + n0) * DD;
    const f16* klp = kl_g + ((size_t)b * SS + n0) * DD;

    const int wm = (wid >> 2) * 32, wn = (wid & 3) * 64;
    float acc[2][8][4];
    #pragma unroll
    for (int i = 0; i < 2; i++)
        #pragma unroll
        for (int j = 0; j < 8; j++)
            #pragma unroll
            for (int e = 0; e < 4; e++) acc[i][j][e] = 0.f;

    auto load_half = [&](int h, uint32_t base) {
        load_tile64<128>(base,         qhp + h * 64, DD, tid);
        load_tile64<256>(base + 16384, khp + h * 64, DD, tid);
        load_tile64<256>(base + 49152, klp + h * 64, DD, tid);
        cp_commit();
    };
    auto compute = [&](uint32_t base) {
        const uint32_t Ah = base, Bh = base + 16384, Bl = base + 49152;
        #pragma unroll
        for (int kt = 0; kt < 4; kt++) {
            uint32_t ah[2][4], bh[8][2], bl[8][2];
            #pragma unroll
            for (int mt = 0; mt < 2; mt++) ldsA(ah[mt], Ah, wm + mt*16, kt, lid);
            #pragma unroll
            for (int nt = 0; nt < 8; nt += 2) ldsB4(bh[nt], bh[nt+1], Bh, wn + nt*8, kt, lid);
            #pragma unroll
            for (int mt = 0; mt < 2; mt++)
                #pragma unroll
                for (int nt = 0; nt < 8; nt++) mma16816(acc[mt][nt], ah[mt], bh[nt]);
            #pragma unroll
            for (int nt = 0; nt < 8; nt += 2) ldsB4(bl[nt], bl[nt+1], Bl, wn + nt*8, kt, lid);
            #pragma unroll
            for (int mt = 0; mt < 2; mt++)
                #pragma unroll
                for (int nt = 0; nt < 8; nt++) mma16816(acc[mt][nt], ah[mt], bl[nt]);
        }
    };

    load_half(0, sb);
    load_half(1, sb + SIM_STG);
    cp_wait<1>(); __syncthreads();
    compute(sb);
    cp_wait<0>(); __syncthreads();
    compute(sb + SIM_STG);

    const int lr = lid >> 2, lc = (lid & 3) * 2;
    float* attb = att + (size_t)b * SS * SS;
    f16* hib = atth + (size_t)b * SS * SS;
    #pragma unroll
    for (int mt = 0; mt < 2; mt++) {
        #pragma unroll
        for (int h2 = 0; h2 < 2; h2++) {
            int row = m0 + wm + mt * 16 + h2 * 8 + lr;
            size_t ro = (size_t)row * SS;
            #pragma unroll
            for (int nt = 0; nt < 8; nt++) {
                int col = n0 + wn + nt * 8 + lc;
                float p0 = fmaxf(acc[mt][nt][h2*2+0], 0.f);
                float p1 = fmaxf(acc[mt][nt][h2*2+1], 0.f);
                float sa0 = p0 * p0, sa1 = p1 * p1;        // att * 2^24
                *(float2*)(attb + ro + col) = make_float2(sa0 * INV_S2, sa1 * INV_S2);
                f162 hp;
                hp.x = __float2half_rn(sa0); hp.y = __float2half_rn(sa1);
                *(f162*)(hib + ro + col) = hp;
            }
        }
    }
}

// ================= big GEMM 2: av = atth @ vT (fp16 1-pass), *gate =========
#define AT_STG 49152    // A 16K | v 32K
#define AT_SMEM (3*AT_STG)
#define AT_NS 64

__global__ __launch_bounds__(512) void attnv_mma(
    const f16* __restrict__ atth, const f16* __restrict__ vt,
    const float* __restrict__ gate, f16* __restrict__ avgh)
{
    extern __shared__ __align__(128) char smem[];
    const uint32_t sb = smem_u32(smem);
    const int tid = threadIdx.x, wid = tid >> 5, lid = tid & 31;
    const int b = blockIdx.y, m0 = blockIdx.x * 128;
    const f16* ahp = atth + (size_t)b * SS * SS + (size_t)m0 * SS;
    const f16* vp  = vt + (size_t)b * SS;

    const int wm = (wid >> 2) * 32, wn = (wid & 3) * 64;
    float acc[2][8][4];
    #pragma unroll
    for (int i = 0; i < 2; i++)
        #pragma unroll
        for (int j = 0; j < 8; j++)
            #pragma unroll
            for (int e = 0; e < 4; e++) acc[i][j][e] = 0.f;

    auto load_slab = [&](int j, int s) {
        uint32_t base = sb + s * AT_STG;
        load_tile64<128>(base,         ahp + j * 64, SS, tid);
        load_tile64<256>(base + 16384, vp + j * 64, ROWS, tid);
        cp_commit();
    };
    auto compute = [&](int s) {
        uint32_t base = sb + s * AT_STG;
        const uint32_t Aa = base, Bv = base + 16384;
        #pragma unroll
        for (int kt = 0; kt < 4; kt++) {
            uint32_t af[2][4], bf[8][2];
            #pragma unroll
            for (int mt = 0; mt < 2; mt++) ldsA(af[mt], Aa, wm + mt*16, kt, lid);
            #pragma unroll
            for (int nt = 0; nt < 8; nt += 2) ldsB4(bf[nt], bf[nt+1], Bv, wn + nt*8, kt, lid);
            #pragma unroll
            for (int mt = 0; mt < 2; mt++)
                #pragma unroll
                for (int nt = 0; nt < 8; nt++) mma16816(acc[mt][nt], af[mt], bf[nt]);
        }
    };

    load_slab(0, 0);
    load_slab(1, 1);
    for (int j = 0; j < AT_NS; j++) {
        if (j + 1 < AT_NS) cp_wait<1>(); else cp_wait<0>();
        __syncthreads();
        if (j + 2 < AT_NS) load_slab(j + 2, (j + 2) % 3);
        compute(j % 3);
    }

    const int lr = lid >> 2, lc = (lid & 3) * 2;
    #pragma unroll
    for (int mt = 0; mt < 2; mt++) {
        #pragma unroll
        for (int h2 = 0; h2 < 2; h2++) {
            size_t grow = (size_t)b * SS + m0 + wm + mt * 16 + h2 * 8 + lr;
            const float* gp = gate + grow * HH;
            f16* hp_ = avgh + grow * HH;
            #pragma unroll
            for (int nt = 0; nt < 8; nt++) {
                int col = wn + nt * 8 + lc;
                float2 g2 = *(const float2*)(gp + col);
                f162 hh;
                hh.x = __float2half_rn(acc[mt][nt][h2*2+0] * g2.x);
                hh.y = __float2half_rn(acc[mt][nt][h2*2+1] * g2.y);
                *(f162*)(hp_ + col) = hh;
            }
        }
    }
}

// ================= launch =================
extern "C" void kernel_launch(void* const* d_in, const int* in_sizes, int n_in,
                              void* d_out, int out_size)
{
    const float* query  = (const float*)d_in[0];
    const float* value  = (const float*)d_in[2];
    const float* ln_g   = (const float*)d_in[3];
    const float* ln_b   = (const float*)d_in[4];
    const float* W_gate = (const float*)d_in[5];
    const float* b_gate = (const float*)d_in[6];
    const float* W_qk   = (const float*)d_in[7];
    const float* b_qk   = (const float*)d_in[8];
    const float* os_g   = (const float*)d_in[9];
    const float* os_b   = (const float*)d_in[10];
    const float* W_out  = (const float*)d_in[11];
    const float* b_out  = (const float*)d_in[12];

    float* out = (float*)d_out;
    float* att = out + (size_t)ROWS * DD;

    f16 *p_nh, *p_vih, *p_wgh, *p_wgl, *p_wqh, *p_wql, *p_woh, *p_wol;
    f16 *p_vr, *p_vT, *p_qh, *p_kh, *p_kl, *p_avgh, *p_atth;
    float *p_gate;
    cudaGetSymbolAddress((void**)&p_nh, g_nh);
    cudaGetSymbolAddress((void**)&p_vih, g_vih);
    cudaGetSymbolAddress((void**)&p_wgh, g_wgh);
    cudaGetSymbolAddress((void**)&p_wgl, g_wgl);
    cudaGetSymbolAddress((void**)&p_wqh, g_wqh);
    cudaGetSymbolAddress((void**)&p_wql, g_wql);
    cudaGetSymbolAddress((void**)&p_woh, g_woh);
    cudaGetSymbolAddress((void**)&p_wol, g_wol);
    cudaGetSymbolAddress((void**)&p_gate, g_gate);
    cudaGetSymbolAddress((void**)&p_vr, g_vr);
    cudaGetSymbolAddress((void**)&p_vT, g_vT);
    cudaGetSymbolAddress((void**)&p_qh, g_qh);
    cudaGetSymbolAddress((void**)&p_kh, g_kh);
    cudaGetSymbolAddress((void**)&p_kl, g_kl);
    cudaGetSymbolAddress((void**)&p_avgh, g_avgh);
    cudaGetSymbolAddress((void**)&p_atth, g_atth);

    constexpr int PSM_256 = 2 * (16384 + 2 * 256 * 128);   // 131072
    constexpr int PSM_128 = 2 * (16384 + 2 * 128 * 128);   // 98304

    cudaFuncSetAttribute(sim_mma,  cudaFuncAttributeMaxDynamicSharedMemorySize, SIM_SMEM);
    cudaFuncSetAttribute(attnv_mma, cudaFuncAttributeMaxDynamicSharedMemorySize, AT_SMEM);
    cudaFuncSetAttribute((const void*)hmma_gemm<256,128,MODE_GATE>, cudaFuncAttributeMaxDynamicSharedMemorySize, PSM_256);
    cudaFuncSetAttribute((const void*)hmma_gemm<256,128,MODE_V>,    cudaFuncAttributeMaxDynamicSharedMemorySize, PSM_256);
    cudaFuncSetAttribute((const void*)hmma_gemm<128,128,MODE_QK>,   cudaFuncAttributeMaxDynamicSharedMemorySize, PSM_128);
    cudaFuncSetAttribute((const void*)hmma_gemm<128,256,MODE_OUT>,  cudaFuncAttributeMaxDynamicSharedMemorySize, PSM_128);

    // prep + splits
    prep_kernel<<<ROWS, 128>>>(query, ln_g, ln_b, p_nh);
    cvt_kernel<<<(ROWS*DD + 255)/256, 256>>>(value, p_vih, ROWS*DD);
    wsplit_all<<<320, 256>>>(W_gate, W_qk, W_out, p_wgh, p_wgl, p_wqh, p_wql, p_woh, p_wol);

    // projections (HMMA, 2-pass)
    hmma_gemm<256,128,MODE_GATE><<<128, 512, PSM_256>>>(
        p_nh, p_wgh, p_wgl, b_gate, nullptr, nullptr,
        p_gate, nullptr, nullptr, nullptr, nullptr);
    hmma_gemm<256,128,MODE_V><<<128, 512, PSM_256>>>(
        p_vih, p_wgh, p_wgl, b_gate, nullptr, nullptr,
        nullptr, p_vr, nullptr, nullptr, nullptr);
    hmma_gemm<128,128,MODE_QK><<<128, 512, PSM_128>>>(
        p_nh, p_wqh, p_wql, b_qk, os_g, os_b,
        nullptr, nullptr, p_qh, p_kh, p_kl);
    transpose_f16<<<dim3(HH/32, ROWS/32), dim3(32, 8)>>>(p_vr, p_vT);

    // attention
    sim_mma<<<dim3(SS/256, SS/128, BB), 512, SIM_SMEM>>>(p_qh, p_kh, p_kl,
        att, p_atth);
    attnv_mma<<<dim3(SS/128, BB), 512, AT_SMEM>>>(p_atth, p_vT, p_gate, p_avgh);

    // output projection (2-pass, descale by 2^-24 in epilogue)
    hmma_gemm<128,256,MODE_OUT><<<128, 512, PSM_128>>>(
        p_avgh, p_woh, p_wol, b_out, nullptr, nullptr,
        out, nullptr, nullptr, nullptr, nullptr);
}

// round 15
// speedup vs baseline: 1.4577x; 1.0905x over previous
#include <cuda_runtime.h>
#include <cuda_fp16.h>
#include <math.h>
#include <stdint.h>

#define BB 4
#define SS 4096
#define DD 128
#define HH 256
#define ROWS (BB*SS)   // 16384
#define INV_S2 (1.0f/16777216.0f)   // 2^-24, exact

typedef __half f16;
typedef __half2 f162;

// ---------------- scratch (no allocations allowed) ----------------
__device__ f16 g_nh[ROWS*DD];
__device__ f16 g_vih[ROWS*DD];
__device__ f16 g_wgh[DD*HH];
__device__ f16 g_wgl[DD*HH];
__device__ f16 g_wqh[DD*DD];
__device__ f16 g_wql[DD*DD];
__device__ f16 g_woh[HH*DD];
__device__ f16 g_wol[HH*DD];
__device__ float g_gate[ROWS*HH];
__device__ f16 g_vr[ROWS*HH];                 // v fp16 [seq][256]
__device__ f16 g_vT[HH*ROWS];                 // v^T fp16 [256][16384]
__device__ f16 g_qh[ROWS*DD];
__device__ f16 g_kh[ROWS*DD];
__device__ f16 g_avgh[ROWS*HH];               // (att@v)*gate, scaled 2^24
__device__ f16 g_atth[(size_t)ROWS*SS];       // att scaled by 2^24 (fp16)

// ================= PTX helpers (base ISA only) =================
__device__ __forceinline__ uint32_t smem_u32(const void* p) {
    uint32_t a;
    asm("{ .reg .u64 t; cvta.to.shared.u64 t, %1; cvt.u32.u64 %0, t; }" : "=r"(a) : "l"(p));
    return a;
}
__device__ __forceinline__ void cp16(uint32_t s, const void* g) {
    asm volatile("cp.async.cg.shared.global [%0], [%1], 16;" :: "r"(s), "l"(g) : "memory");
}
__device__ __forceinline__ void cp_commit() { asm volatile("cp.async.commit_group;" ::: "memory"); }
template<int N> __device__ __forceinline__ void cp_wait() {
    asm volatile("cp.async.wait_group %0;" :: "n"(N) : "memory");
}
__device__ __forceinline__ void ldm_x4(uint32_t &r0, uint32_t &r1, uint32_t &r2, uint32_t &r3, uint32_t a) {
    asm volatile("ldmatrix.sync.aligned.m8n8.x4.shared.b16 {%0,%1,%2,%3}, [%4];"
        : "=r"(r0), "=r"(r1), "=r"(r2), "=r"(r3) : "r"(a));
}
__device__ __forceinline__ void mma16816(float (&c)[4], const uint32_t (&a)[4], const uint32_t (&b)[2]) {
    asm volatile("mma.sync.aligned.m16n8k16.row.col.f32.f16.f16.f32 "
        "{%0,%1,%2,%3}, {%4,%5,%6,%7}, {%8,%9}, {%0,%1,%2,%3};"
        : "+f"(c[0]), "+f"(c[1]), "+f"(c[2]), "+f"(c[3])
        : "r"(a[0]), "r"(a[1]), "r"(a[2]), "r"(a[3]), "r"(b[0]), "r"(b[1]));
}
// A-frag (m16k16) for one 16-row tile
__device__ __forceinline__ void ldsA(uint32_t (&a)[4], uint32_t base, int mrow, int kt, int lid) {
    int g = lid >> 3, r = lid & 7;
    int row = mrow + ((g & 1) << 3) + r;
    int ch = (kt << 1) + (g >> 1);
    ldm_x4(a[0], a[1], a[2], a[3], base + row * 128 + ((ch ^ (row & 7)) << 4));
}
// TWO adjacent B-frags (k16n8 each) in ONE ldmatrix.x4
__device__ __forceinline__ void ldsB4(uint32_t (&b0)[2], uint32_t (&b1)[2],
                                      uint32_t base, int nrow, int kt, int lid) {
    int g = lid >> 3, r = lid & 7;
    int row = nrow + ((g >> 1) << 3) + r;
    int ch = (kt << 1) + (g & 1);
    ldm_x4(b0[0], b0[1], b1[0], b1[1], base + row * 128 + ((ch ^ (row & 7)) << 4));
}
// 512-thread tile loader: [NROWS x 64] f16 k-contiguous -> swizzled smem
template<int NROWS>
__device__ __forceinline__ void load_tile64(uint32_t sbase, const f16* g, size_t rstride, int tid) {
    #pragma unroll
    for (int i = 0; i < NROWS * 8; i += 512) {
        int idx = i + tid;
        int r = idx >> 3, c = idx & 7;
        cp16(sbase + r * 128 + ((c ^ (r & 7)) << 4), g + (size_t)r * rstride + c * 8);
    }
}
__device__ __forceinline__ float silu_f(float x) { return x / (1.0f + expf(-x)); }
__device__ __forceinline__ void split2(float x, f16 &h, f16 &l) {
    h = __float2half_rn(x);
    l = __float2half_rn(x - __half2float(h));
}

// ================= kernel 1: rope + layernorm -> fp16 =================
__global__ void prep_kernel(const float* __restrict__ q, const float* __restrict__ g,
                            const float* __restrict__ b, f16* __restrict__ nh) {
    const int row = blockIdx.x;
    const int d = threadIdx.x;
    const int t = row & (SS - 1);
    float x = q[(size_t)row * DD + d];
    float y = x;
    if (d < 32) {
        int j = d >> 1;
        double dinv = pow(10000.0, -(double)j / 16.0);
        float f = (float)t * (float)dinv;
        float c = cosf(f), s = sinf(f);
        float partner = __shfl_xor_sync(0xffffffffu, x, 1);
        y = (d & 1) ? (x * c + partner * s) : (x * c - partner * s);
    }
    __shared__ float red[4];
    float v = y;
    #pragma unroll
    for (int o2 = 16; o2; o2 >>= 1) v += __shfl_xor_sync(0xffffffffu, v, o2);
    if ((threadIdx.x & 31) == 0) red[threadIdx.x >> 5] = v;
    __syncthreads();
    float mu = (red[0] + red[1] + red[2] + red[3]) * (1.0f / 128.0f);
    float dv = y - mu;
    float v2 = dv * dv;
    __syncthreads();
    #pragma unroll
    for (int o2 = 16; o2; o2 >>= 1) v2 += __shfl_xor_sync(0xffffffffu, v2, o2);
    if ((threadIdx.x & 31) == 0) red[threadIdx.x >> 5] = v2;
    __syncthreads();
    float var = (red[0] + red[1] + red[2] + red[3]) * (1.0f / 128.0f);
    float rs = rsqrtf(var + 1e-5f);
    float out = dv * rs * g[d] + b[d];
    nh[(size_t)row * DD + d] = __float2half_rn(out);
}

// ================= elementwise f32 -> fp16 convert =================
__global__ void cvt_kernel(const float* __restrict__ x, f16* __restrict__ xh, int n) {
    int i = blockIdx.x * 256 + threadIdx.x;
    if (i < n) xh[i] = __float2half_rn(x[i]);
}

// ================= all weights transpose+split in ONE launch =================
__global__ void wsplit_all(const float* __restrict__ Wg, const float* __restrict__ Wq,
                           const float* __restrict__ Wo,
                           f16* __restrict__ wgh, f16* __restrict__ wgl,
                           f16* __restrict__ wqh, f16* __restrict__ wql,
                           f16* __restrict__ woh, f16* __restrict__ wol) {
    int i = blockIdx.x * 256 + threadIdx.x;
    const float* W; f16 *wh, *wl; int K, N, off;
    if (i < 32768)       { W = Wg; wh = wgh; wl = wgl; K = 128; N = 256; off = i; }
    else if (i < 49152)  { W = Wq; wh = wqh; wl = wql; K = 128; N = 128; off = i - 32768; }
    else if (i < 81920)  { W = Wo; wh = woh; wl = wol; K = 256; N = 128; off = i - 49152; }
    else return;
    int k = off / N, n = off % N;
    f16 h, l; split2(W[(size_t)k * N + n], h, l);
    wh[(size_t)n * K + k] = h;
    wl[(size_t)n * K + k] = l;
}

// ================= fp16 transpose: [16384][256] -> [256][16384] ============
__global__ void transpose_f16(const f16* __restrict__ v, f16* __restrict__ vt) {
    __shared__ f16 tile[32][33];
    int x = blockIdx.x * 32 + threadIdx.x;
    int y = blockIdx.y * 32 + threadIdx.y;
    #pragma unroll
    for (int dy = 0; dy < 32; dy += 8)
        tile[threadIdx.y + dy][threadIdx.x] = v[(size_t)(y + dy) * HH + x];
    __syncthreads();
    int xo = blockIdx.y * 32 + threadIdx.x;
    int yo = blockIdx.x * 32 + threadIdx.y;
    #pragma unroll
    for (int dy = 0; dy < 32; dy += 8)
        vt[(size_t)(yo + dy) * ROWS + xo] = tile[threadIdx.x][threadIdx.y + dy];
}

// ====== generic HMMA projection GEMM, 2-pass: A_hi x (B_hi + B_lo) =========
#define MODE_GATE 0
#define MODE_V    1
#define MODE_QK   2
#define MODE_OUT  3   // acc scaled by 2^24; multiply by INV_S2 before bias

template<int NDIM, int KDIM, int MODE>
__global__ __launch_bounds__(512) void hmma_gemm(
    const f16* __restrict__ Ah_g,
    const f16* __restrict__ Bh_g, const f16* __restrict__ Bl_g,
    const float* __restrict__ bias, const float* __restrict__ gam,
    const float* __restrict__ bet,
    float* __restrict__ O0f, f16* __restrict__ O0h,
    f16* __restrict__ qh, f16* __restrict__ kh)
{
    constexpr int NSLAB = KDIM / 64;
    constexpr int BSTG = NDIM * 128;
    constexpr int STG = 16384 + 2 * BSTG;
    constexpr int NT = NDIM / 32;
    extern __shared__ __align__(128) char smem[];
    const uint32_t sb = smem_u32(smem);
    const int tid = threadIdx.x, wid = tid >> 5, lid = tid & 31;
    const int m0 = blockIdx.x * 128;
    const f16* Ahp = Ah_g + (size_t)m0 * KDIM;

    const int wm = (wid >> 2) * 32;
    const int wn = (wid & 3) * (NDIM / 4);
    float acc[2][NT][4];
    #pragma unroll
    for (int i = 0; i < 2; i++)
        #pragma unroll
        for (int j = 0; j < NT; j++)
            #pragma unroll
            for (int e = 0; e < 4; e++) acc[i][j][e] = 0.f;

    auto load_slab = [&](int s, uint32_t base) {
        load_tile64<128>(base,          Ahp + s * 64, KDIM, tid);
        load_tile64<NDIM>(base + 16384, Bh_g + s * 64, KDIM, tid);
        load_tile64<NDIM>(base + 16384 + BSTG, Bl_g + s * 64, KDIM, tid);
        cp_commit();
    };
    auto compute = [&](uint32_t base) {
        const uint32_t Ah = base;
        const uint32_t Bh = base + 16384, Bl = base + 16384 + BSTG;
        #pragma unroll
        for (int kt = 0; kt < 4; kt++) {
            uint32_t ah[2][4], bh[NT][2], bl[NT][2];
            #pragma unroll
            for (int mt = 0; mt < 2; mt++) ldsA(ah[mt], Ah, wm + mt*16, kt, lid);
            #pragma unroll
            for (int nt = 0; nt < NT; nt += 2) ldsB4(bh[nt], bh[nt+1], Bh, wn + nt*8, kt, lid);
            #pragma unroll
            for (int mt = 0; mt < 2; mt++)
                #pragma unroll
                for (int nt = 0; nt < NT; nt++) mma16816(acc[mt][nt], ah[mt], bh[nt]);
            #pragma unroll
            for (int nt = 0; nt < NT; nt += 2) ldsB4(bl[nt], bl[nt+1], Bl, wn + nt*8, kt, lid);
            #pragma unroll
            for (int mt = 0; mt < 2; mt++)
                #pragma unroll
                for (int nt = 0; nt < NT; nt++) mma16816(acc[mt][nt], ah[mt], bl[nt]);
        }
    };

    load_slab(0, sb);
    if (NSLAB > 1) load_slab(1, sb + STG);
    #pragma unroll
    for (int j = 0; j < NSLAB; j++) {
        if (j + 1 < NSLAB) cp_wait<1>(); else cp_wait<0>();
        __syncthreads();
        compute(sb + (j & 1) * STG);
        if (j + 2 < NSLAB) { __syncthreads(); load_slab(j + 2, sb + (j & 1) * STG); }
    }

    const float scl = (MODE == MODE_OUT) ? INV_S2 : 1.0f;
    const int lr = lid >> 2, lc = (lid & 3) * 2;
    #pragma unroll
    for (int mt = 0; mt < 2; mt++) {
        #pragma unroll
        for (int h2 = 0; h2 < 2; h2++) {
            const int row = m0 + wm + mt * 16 + h2 * 8 + lr;
            #pragma unroll
            for (int nt = 0; nt < NT; nt++) {
                const int col = wn + nt * 8 + lc;
                float x0 = acc[mt][nt][h2*2+0] * scl + bias[col];
                float x1 = acc[mt][nt][h2*2+1] * scl + bias[col+1];
                if (MODE == MODE_GATE) {
                    *(float2*)(O0f + (size_t)row * NDIM + col) = make_float2(silu_f(x0), silu_f(x1));
                } else if (MODE == MODE_V) {
                    f162 p;
                    p.x = __float2half_rn(silu_f(x0)); p.y = __float2half_rn(silu_f(x1));
                    *(f162*)(O0h + (size_t)row * NDIM + col) = p;
                } else if (MODE == MODE_QK) {
                    float y0 = silu_f(x0), y1 = silu_f(x1);
                    float q0 = y0 * gam[col] + bet[col], q1 = y1 * gam[col+1] + bet[col+1];
                    float k0 = y0 * gam[NDIM+col] + bet[NDIM+col], k1 = y1 * gam[NDIM+col+1] + bet[NDIM+col+1];
                    f162 hp;
                    hp.x = __float2half_rn(q0); hp.y = __float2half_rn(q1);
                    *(f162*)(qh + (size_t)row * NDIM + col) = hp;
                    hp.x = __float2half_rn(k0); hp.y = __float2half_rn(k1);
                    *(f162*)(kh + (size_t)row * NDIM + col) = hp;
                } else {
                    *(float2*)(O0f + (size_t)row * NDIM + col) = make_float2(x0, x1);
                }
            }
        }
    }
}

// ======== big GEMM 1: att = relu(q@k^T/S)^2 (fp16 1-pass q_hi x k_hi) ======
#define SIM_STG 49152   // Ah 16K | Bh 32K
#define SIM_SMEM (2*SIM_STG)

__global__ __launch_bounds__(512) void sim_mma(
    const f16* __restrict__ qh_g, const f16* __restrict__ kh_g,
    float* __restrict__ att, f16* __restrict__ atth)
{
    extern __shared__ __align__(128) char smem[];
    const uint32_t sb = smem_u32(smem);
    const int tid = threadIdx.x, wid = tid >> 5, lid = tid & 31;
    const int b = blockIdx.z, m0 = blockIdx.y * 128, n0 = blockIdx.x * 256;
    const f16* qhp = qh_g + ((size_t)b * SS + m0) * DD;
    const f16* khp = kh_g + ((size_t)b * SS + n0) * DD;

    const int wm = (wid >> 2) * 32, wn = (wid & 3) * 64;
    float acc[2][8][4];
    #pragma unroll
    for (int i = 0; i < 2; i++)
        #pragma unroll
        for (int j = 0; j < 8; j++)
            #pragma unroll
            for (int e = 0; e < 4; e++) acc[i][j][e] = 0.f;

    auto load_half = [&](int h, uint32_t base) {
        load_tile64<128>(base,         qhp + h * 64, DD, tid);
        load_tile64<256>(base + 16384, khp + h * 64, DD, tid);
        cp_commit();
    };
    auto compute = [&](uint32_t base) {
        const uint32_t Ah = base, Bh = base + 16384;
        #pragma unroll
        for (int kt = 0; kt < 4; kt++) {
            uint32_t ah[2][4], bh[8][2];
            #pragma unroll
            for (int mt = 0; mt < 2; mt++) ldsA(ah[mt], Ah, wm + mt*16, kt, lid);
            #pragma unroll
            for (int nt = 0; nt < 8; nt += 2) ldsB4(bh[nt], bh[nt+1], Bh, wn + nt*8, kt, lid);
            #pragma unroll
            for (int mt = 0; mt < 2; mt++)
                #pragma unroll
                for (int nt = 0; nt < 8; nt++) mma16816(acc[mt][nt], ah[mt], bh[nt]);
        }
    };

    load_half(0, sb);
    load_half(1, sb + SIM_STG);
    cp_wait<1>(); __syncthreads();
    compute(sb);
    cp_wait<0>(); __syncthreads();
    compute(sb + SIM_STG);

    const int lr = lid >> 2, lc = (lid & 3) * 2;
    float* attb = att + (size_t)b * SS * SS;
    f16* hib = atth + (size_t)b * SS * SS;
    #pragma unroll
    for (int mt = 0; mt < 2; mt++) {
        #pragma unroll
        for (int h2 = 0; h2 < 2; h2++) {
            int row = m0 + wm + mt * 16 + h2 * 8 + lr;
            size_t ro = (size_t)row * SS;
            #pragma unroll
            for (int nt = 0; nt < 8; nt++) {
                int col = n0 + wn + nt * 8 + lc;
                float p0 = fmaxf(acc[mt][nt][h2*2+0], 0.f);
                float p1 = fmaxf(acc[mt][nt][h2*2+1], 0.f);
                float sa0 = p0 * p0, sa1 = p1 * p1;        // att * 2^24
                *(float2*)(attb + ro + col) = make_float2(sa0 * INV_S2, sa1 * INV_S2);
                f162 hp;
                hp.x = __float2half_rn(sa0); hp.y = __float2half_rn(sa1);
                *(f162*)(hib + ro + col) = hp;
            }
        }
    }
}

// ================= big GEMM 2: av = atth @ vT (fp16 1-pass), *gate =========
#define AT_STG 49152    // A 16K | v 32K
#define AT_SMEM (3*AT_STG)
#define AT_NS 64

__global__ __launch_bounds__(512) void attnv_mma(
    const f16* __restrict__ atth, const f16* __restrict__ vt,
    const float* __restrict__ gate, f16* __restrict__ avgh)
{
    extern __shared__ __align__(128) char smem[];
    const uint32_t sb = smem_u32(smem);
    const int tid = threadIdx.x, wid = tid >> 5, lid = tid & 31;
    const int b = blockIdx.y, m0 = blockIdx.x * 128;
    const f16* ahp = atth + (size_t)b * SS * SS + (size_t)m0 * SS;
    const f16* vp  = vt + (size_t)b * SS;

    const int wm = (wid >> 2) * 32, wn = (wid & 3) * 64;
    float acc[2][8][4];
    #pragma unroll
    for (int i = 0; i < 2; i++)
        #pragma unroll
        for (int j = 0; j < 8; j++)
            #pragma unroll
            for (int e = 0; e < 4; e++) acc[i][j][e] = 0.f;

    auto load_slab = [&](int j, int s) {
        uint32_t base = sb + s * AT_STG;
        load_tile64<128>(base,         ahp + j * 64, SS, tid);
        load_tile64<256>(base + 16384, vp + j * 64, ROWS, tid);
        cp_commit();
    };
    auto compute = [&](int s) {
        uint32_t base = sb + s * AT_STG;
        const uint32_t Aa = base, Bv = base + 16384;
        #pragma unroll
        for (int kt = 0; kt < 4; kt++) {
            uint32_t af[2][4], bf[8][2];
            #pragma unroll
            for (int mt = 0; mt < 2; mt++) ldsA(af[mt], Aa, wm + mt*16, kt, lid);
            #pragma unroll
            for (int nt = 0; nt < 8; nt += 2) ldsB4(bf[nt], bf[nt+1], Bv, wn + nt*8, kt, lid);
            #pragma unroll
            for (int mt = 0; mt < 2; mt++)
                #pragma unroll
                for (int nt = 0; nt < 8; nt++) mma16816(acc[mt][nt], af[mt], bf[nt]);
        }
    };

    load_slab(0, 0);
    load_slab(1, 1);
    for (int j = 0; j < AT_NS; j++) {
        if (j + 1 < AT_NS) cp_wait<1>(); else cp_wait<0>();
        __syncthreads();
        if (j + 2 < AT_NS) load_slab(j + 2, (j + 2) % 3);
        compute(j % 3);
    }

    const int lr = lid >> 2, lc = (lid & 3) * 2;
    #pragma unroll
    for (int mt = 0; mt < 2; mt++) {
        #pragma unroll
        for (int h2 = 0; h2 < 2; h2++) {
            size_t grow = (size_t)b * SS + m0 + wm + mt * 16 + h2 * 8 + lr;
            const float* gp = gate + grow * HH;
            f16* hp_ = avgh + grow * HH;
            #pragma unroll
            for (int nt = 0; nt < 8; nt++) {
                int col = wn + nt * 8 + lc;
                float2 g2 = *(const float2*)(gp + col);
                f162 hh;
                hh.x = __float2half_rn(acc[mt][nt][h2*2+0] * g2.x);
                hh.y = __float2half_rn(acc[mt][nt][h2*2+1] * g2.y);
                *(f162*)(hp_ + col) = hh;
            }
        }
    }
}

// ================= launch =================
extern "C" void kernel_launch(void* const* d_in, const int* in_sizes, int n_in,
                              void* d_out, int out_size)
{
    const float* query  = (const float*)d_in[0];
    const float* value  = (const float*)d_in[2];
    const float* ln_g   = (const float*)d_in[3];
    const float* ln_b   = (const float*)d_in[4];
    const float* W_gate = (const float*)d_in[5];
    const float* b_gate = (const float*)d_in[6];
    const float* W_qk   = (const float*)d_in[7];
    const float* b_qk   = (const float*)d_in[8];
    const float* os_g   = (const float*)d_in[9];
    const float* os_b   = (const float*)d_in[10];
    const float* W_out  = (const float*)d_in[11];
    const float* b_out  = (const float*)d_in[12];

    float* out = (float*)d_out;
    float* att = out + (size_t)ROWS * DD;

    f16 *p_nh, *p_vih, *p_wgh, *p_wgl, *p_wqh, *p_wql, *p_woh, *p_wol;
    f16 *p_vr, *p_vT, *p_qh, *p_kh, *p_avgh, *p_atth;
    float *p_gate;
    cudaGetSymbolAddress((void**)&p_nh, g_nh);
    cudaGetSymbolAddress((void**)&p_vih, g_vih);
    cudaGetSymbolAddress((void**)&p_wgh, g_wgh);
    cudaGetSymbolAddress((void**)&p_wgl, g_wgl);
    cudaGetSymbolAddress((void**)&p_wqh, g_wqh);
    cudaGetSymbolAddress((void**)&p_wql, g_wql);
    cudaGetSymbolAddress((void**)&p_woh, g_woh);
    cudaGetSymbolAddress((void**)&p_wol, g_wol);
    cudaGetSymbolAddress((void**)&p_gate, g_gate);
    cudaGetSymbolAddress((void**)&p_vr, g_vr);
    cudaGetSymbolAddress((void**)&p_vT, g_vT);
    cudaGetSymbolAddress((void**)&p_qh, g_qh);
    cudaGetSymbolAddress((void**)&p_kh, g_kh);
    cudaGetSymbolAddress((void**)&p_avgh, g_avgh);
    cudaGetSymbolAddress((void**)&p_atth, g_atth);

    constexpr int PSM_256 = 2 * (16384 + 2 * 256 * 128);   // 131072
    constexpr int PSM_128 = 2 * (16384 + 2 * 128 * 128);   // 98304

    cudaFuncSetAttribute(sim_mma,  cudaFuncAttributeMaxDynamicSharedMemorySize, SIM_SMEM);
    cudaFuncSetAttribute(attnv_mma, cudaFuncAttributeMaxDynamicSharedMemorySize, AT_SMEM);
    cudaFuncSetAttribute((const void*)hmma_gemm<256,128,MODE_GATE>, cudaFuncAttributeMaxDynamicSharedMemorySize, PSM_256);
    cudaFuncSetAttribute((const void*)hmma_gemm<256,128,MODE_V>,    cudaFuncAttributeMaxDynamicSharedMemorySize, PSM_256);
    cudaFuncSetAttribute((const void*)hmma_gemm<128,128,MODE_QK>,   cudaFuncAttributeMaxDynamicSharedMemorySize, PSM_128);
    cudaFuncSetAttribute((const void*)hmma_gemm<128,256,MODE_OUT>,  cudaFuncAttributeMaxDynamicSharedMemorySize, PSM_128);

    // prep + splits
    prep_kernel<<<ROWS, 128>>>(query, ln_g, ln_b, p_nh);
    cvt_kernel<<<(ROWS*DD + 255)/256, 256>>>(value, p_vih, ROWS*DD);
    wsplit_all<<<320, 256>>>(W_gate, W_qk, W_out, p_wgh, p_wgl, p_wqh, p_wql, p_woh, p_wol);

    // projections (HMMA, 2-pass)
    hmma_gemm<256,128,MODE_GATE><<<128, 512, PSM_256>>>(
        p_nh, p_wgh, p_wgl, b_gate, nullptr, nullptr,
        p_gate, nullptr, nullptr, nullptr);
    hmma_gemm<256,128,MODE_V><<<128, 512, PSM_256>>>(
        p_vih, p_wgh, p_wgl, b_gate, nullptr, nullptr,
        nullptr, p_vr, nullptr, nullptr);
    hmma_gemm<128,128,MODE_QK><<<128, 512, PSM_128>>>(
        p_nh, p_wqh, p_wql, b_qk, os_g, os_b,
        nullptr, nullptr, p_qh, p_kh);
    transpose_f16<<<dim3(HH/32, ROWS/32), dim3(32, 8)>>>(p_vr, p_vT);

    // attention
    sim_mma<<<dim3(SS/256, SS/128, BB), 512, SIM_SMEM>>>(p_qh, p_kh, att, p_atth);
    attnv_mma<<<dim3(SS/128, BB), 512, AT_SMEM>>>(p_atth, p_vT, p_gate, p_avgh);

    // output projection (2-pass, descale by 2^-24 in epilogue)
    hmma_gemm<128,256,MODE_OUT><<<128, 512, PSM_128>>>(
        p_avgh, p_woh, p_wol, b_out, nullptr, nullptr,
        out, nullptr, nullptr, nullptr);
}